// round 1
// baseline (speedup 1.0000x reference)
#include <cuda_runtime.h>
#include <float.h>
#include <math.h>

// Problem constants
#define NB 8
#define NN 256
#define NM 512
#define NE 1024
#define NH 32
#define ND 32
#define NEXT 768   // N + M

#define SCALING_F 0.17677669529663687f  // 32^-0.5

// ---------------- device scratch (static, allowed) ----------------
static __device__ float g_q [NB*NN*NE];
static __device__ float g_k [NB*NN*NE];
static __device__ float g_v [NB*NN*NE];
static __device__ float g_ve[NB*NN*NE];
static __device__ float g_attn[(long long)NB*NH*NN*NEXT]; // logits -> probs (in place)
static __device__ float g_xo [NB*NN*NE];
static __device__ float g_vec[NB*NN*3*NE];

// ============================================================================
// Tiled fp32 GEMM:  C[r][j] = alpha * sum_k A[r][k] * W[j][k]
// (i.e. C = A @ W^T, both row-major, K = NE = 1024, Ncols = NE)
// Tile 64x64, K-tile 16, 256 threads, 4x4 per thread.
// xlayout=1: A is x with layout [N, B, E]; logical row r = b*NN + n.
// ============================================================================
__global__ __launch_bounds__(256) void gemm64(const float* __restrict__ A,
                                              const float* __restrict__ W,
                                              float* __restrict__ C,
                                              float alpha, int xlayout)
{
    __shared__ float As[16][64];
    __shared__ float Bs[16][64];

    const int tid  = threadIdx.x;
    const int tn   = tid & 15;
    const int tm   = tid >> 4;
    const int row0 = blockIdx.y << 6;
    const int col0 = blockIdx.x << 6;

    const int la_row = tid >> 2;         // 0..63
    const int la_k   = (tid & 3) << 2;   // 0,4,8,12

    const float* aRow;
    {
        int r = row0 + la_row;
        if (xlayout) {
            int b = r >> 8;      // / NN (NN = 256)
            int n = r & 255;
            aRow = A + ((long long)n * NB + b) * NE;
        } else {
            aRow = A + (long long)r * NE;
        }
    }
    const float* wRow = W + (long long)(col0 + la_row) * NE;

    float acc[4][4];
    #pragma unroll
    for (int i = 0; i < 4; i++)
        #pragma unroll
        for (int j = 0; j < 4; j++) acc[i][j] = 0.f;

    for (int k0 = 0; k0 < NE; k0 += 16) {
        float4 a4 = *(const float4*)(aRow + k0 + la_k);
        float4 b4 = *(const float4*)(wRow + k0 + la_k);
        As[la_k+0][la_row] = a4.x;
        As[la_k+1][la_row] = a4.y;
        As[la_k+2][la_row] = a4.z;
        As[la_k+3][la_row] = a4.w;
        Bs[la_k+0][la_row] = b4.x;
        Bs[la_k+1][la_row] = b4.y;
        Bs[la_k+2][la_row] = b4.z;
        Bs[la_k+3][la_row] = b4.w;
        __syncthreads();

        #pragma unroll
        for (int k = 0; k < 16; k++) {
            float4 av = *(const float4*)&As[k][tm << 2];
            float4 bv = *(const float4*)&Bs[k][tn << 2];
            acc[0][0] = fmaf(av.x, bv.x, acc[0][0]);
            acc[0][1] = fmaf(av.x, bv.y, acc[0][1]);
            acc[0][2] = fmaf(av.x, bv.z, acc[0][2]);
            acc[0][3] = fmaf(av.x, bv.w, acc[0][3]);
            acc[1][0] = fmaf(av.y, bv.x, acc[1][0]);
            acc[1][1] = fmaf(av.y, bv.y, acc[1][1]);
            acc[1][2] = fmaf(av.y, bv.z, acc[1][2]);
            acc[1][3] = fmaf(av.y, bv.w, acc[1][3]);
            acc[2][0] = fmaf(av.z, bv.x, acc[2][0]);
            acc[2][1] = fmaf(av.z, bv.y, acc[2][1]);
            acc[2][2] = fmaf(av.z, bv.z, acc[2][2]);
            acc[2][3] = fmaf(av.z, bv.w, acc[2][3]);
            acc[3][0] = fmaf(av.w, bv.x, acc[3][0]);
            acc[3][1] = fmaf(av.w, bv.y, acc[3][1]);
            acc[3][2] = fmaf(av.w, bv.z, acc[3][2]);
            acc[3][3] = fmaf(av.w, bv.w, acc[3][3]);
        }
        __syncthreads();
    }

    #pragma unroll
    for (int i = 0; i < 4; i++) {
        float4 o;
        o.x = alpha * acc[i][0];
        o.y = alpha * acc[i][1];
        o.z = alpha * acc[i][2];
        o.w = alpha * acc[i][3];
        *(float4*)(C + (long long)(row0 + (tm << 2) + i) * NE + col0 + (tn << 2)) = o;
    }
}

// ============================================================================
// QK^T tile kernel: logits[b,h,n,m] = q.k + bias, masked. 64(n) x 64(m) tile,
// K = 32 (head dim), extended K rows resolved through outcell_index gather.
// ============================================================================
__global__ __launch_bounds__(256) void qk64(const float* __restrict__ bias,
                                            const int*   __restrict__ oidx,
                                            const unsigned char* __restrict__ pmask,
                                            const unsigned char* __restrict__ emask)
{
    __shared__ float qs[32][64];
    __shared__ float ks[32][64];

    const int tid = threadIdx.x;
    const int bh  = blockIdx.z;
    const int b   = bh >> 5;       // / NH
    const int h   = bh & 31;
    const int n0  = blockIdx.y << 6;
    const int m0  = blockIdx.x << 6;

    #pragma unroll
    for (int ph = 0; ph < 2; ph++) {
        int idx = tid + (ph << 8);
        int rr  = idx >> 3;           // 0..63
        int kq  = (idx & 7) << 2;     // 0..28 step 4
        float4 a4 = *(const float4*)(g_q + ((long long)(b*NN + n0 + rr))*NE + h*ND + kq);
        qs[kq+0][rr] = a4.x; qs[kq+1][rr] = a4.y; qs[kq+2][rr] = a4.z; qs[kq+3][rr] = a4.w;
        int m = m0 + rr;
        int krow = (m < NN) ? m : oidx[b*NM + m - NN];
        float4 k4 = *(const float4*)(g_k + ((long long)(b*NN + krow))*NE + h*ND + kq);
        ks[kq+0][rr] = k4.x; ks[kq+1][rr] = k4.y; ks[kq+2][rr] = k4.z; ks[kq+3][rr] = k4.w;
    }
    __syncthreads();

    const int tn = tid & 15, tm = tid >> 4;
    float acc[4][4];
    #pragma unroll
    for (int i = 0; i < 4; i++)
        #pragma unroll
        for (int j = 0; j < 4; j++) acc[i][j] = 0.f;

    #pragma unroll
    for (int k = 0; k < 32; k++) {
        float4 av = *(const float4*)&qs[k][tm << 2];
        float4 bv = *(const float4*)&ks[k][tn << 2];
        acc[0][0] = fmaf(av.x, bv.x, acc[0][0]);
        acc[0][1] = fmaf(av.x, bv.y, acc[0][1]);
        acc[0][2] = fmaf(av.x, bv.z, acc[0][2]);
        acc[0][3] = fmaf(av.x, bv.w, acc[0][3]);
        acc[1][0] = fmaf(av.y, bv.x, acc[1][0]);
        acc[1][1] = fmaf(av.y, bv.y, acc[1][1]);
        acc[1][2] = fmaf(av.y, bv.z, acc[1][2]);
        acc[1][3] = fmaf(av.y, bv.w, acc[1][3]);
        acc[2][0] = fmaf(av.z, bv.x, acc[2][0]);
        acc[2][1] = fmaf(av.z, bv.y, acc[2][1]);
        acc[2][2] = fmaf(av.z, bv.z, acc[2][2]);
        acc[2][3] = fmaf(av.z, bv.w, acc[2][3]);
        acc[3][0] = fmaf(av.w, bv.x, acc[3][0]);
        acc[3][1] = fmaf(av.w, bv.y, acc[3][1]);
        acc[3][2] = fmaf(av.w, bv.z, acc[3][2]);
        acc[3][3] = fmaf(av.w, bv.w, acc[3][3]);
    }

    const long long base = (long long)(b*NH + h) * NN;
    #pragma unroll
    for (int i = 0; i < 4; i++) {
        int n = n0 + (tm << 2) + i;
        bool pn = pmask[b*NN + n] != 0;
        long long rowoff = (base + n) * NEXT;
        #pragma unroll
        for (int j = 0; j < 4; j++) {
            int m = m0 + (tn << 2) + j;
            bool fm = (m < NN) ? (pmask[b*NN + m] != 0)
                               : (emask[b*NM + m - NN] != 0);
            float v = acc[i][j] + bias[rowoff + m];
            if (pn || fm) v = -FLT_MAX;
            g_attn[rowoff + m] = v;
        }
    }
}

// ============================================================================
// Row softmax over 768 elements (in place). One block per (b,h,n) row.
// ============================================================================
__global__ __launch_bounds__(256) void softmax768()
{
    long long row = blockIdx.x;
    float* p = g_attn + row * NEXT;
    const int tid = threadIdx.x;

    float v0 = p[tid], v1 = p[tid + 256], v2 = p[tid + 512];
    float mx = fmaxf(v0, fmaxf(v1, v2));

    __shared__ float red[8];
    #pragma unroll
    for (int o = 16; o > 0; o >>= 1)
        mx = fmaxf(mx, __shfl_xor_sync(0xffffffffu, mx, o));
    if ((tid & 31) == 0) red[tid >> 5] = mx;
    __syncthreads();
    if (tid < 32) {
        float m2 = (tid < 8) ? red[tid] : -FLT_MAX;
        #pragma unroll
        for (int o = 4; o > 0; o >>= 1)
            m2 = fmaxf(m2, __shfl_xor_sync(0xffffffffu, m2, o));
        if (tid == 0) red[0] = m2;
    }
    __syncthreads();
    mx = red[0];
    __syncthreads();

    float e0 = expf(v0 - mx), e1 = expf(v1 - mx), e2 = expf(v2 - mx);
    float s = e0 + e1 + e2;
    #pragma unroll
    for (int o = 16; o > 0; o >>= 1)
        s += __shfl_xor_sync(0xffffffffu, s, o);
    if ((tid & 31) == 0) red[tid >> 5] = s;
    __syncthreads();
    if (tid < 32) {
        float s2 = (tid < 8) ? red[tid] : 0.f;
        #pragma unroll
        for (int o = 4; o > 0; o >>= 1)
            s2 += __shfl_xor_sync(0xffffffffu, s2, o);
        if (tid == 0) red[0] = s2;
    }
    __syncthreads();
    float inv = 1.f / red[0];

    p[tid]       = e0 * inv;
    p[tid + 256] = e1 * inv;
    p[tid + 512] = e2 * inv;
}

// ============================================================================
// Fused PV + vec kernel.
//   xo [b,n,h,d]      = sum_m probs[b,h,n,m] * ve_ext[b,m,h,d]
//   vec[b,n,c,h,d]    = sum_m probs[b,h,n,m] * delta[b,n,m,c] * v_ext[b,m,h,d]
// delta computed on the fly from pos/expand_pos (masks applied).
// Block: (b, h, 16-row n-tile), 512 threads = 16(n) x 32(d). m tiled by 64.
// ============================================================================
__global__ __launch_bounds__(512) void pv_vec(const float* __restrict__ pos,
                                              const float* __restrict__ epos,
                                              const int*   __restrict__ oidx,
                                              const unsigned char* __restrict__ pmask,
                                              const unsigned char* __restrict__ emask)
{
    __shared__ float vs [64][32];
    __shared__ float ves[64][32];
    __shared__ float ps [16][64];
    __shared__ float dxs[16][64];
    __shared__ float dys[16][64];
    __shared__ float dzs[16][64];

    const int b  = blockIdx.z;
    const int h  = blockIdx.y;
    const int n0 = blockIdx.x << 4;
    const int tid = threadIdx.x;
    const int tn = tid >> 5;   // 0..15
    const int td = tid & 31;   // 0..31

    float accxo = 0.f, accx = 0.f, accy = 0.f, accz = 0.f;

    for (int m0 = 0; m0 < NEXT; m0 += 64) {
        // ---- load v / ve tiles (gathered extension) ----
        {
            int rr = tid >> 3;            // 0..63
            int kq = (tid & 7) << 2;      // 0..28
            int m  = m0 + rr;
            int row = (m < NN) ? m : oidx[b*NM + m - NN];
            long long off = ((long long)(b*NN + row))*NE + h*ND + kq;
            float4 v4  = *(const float4*)(g_v  + off);
            float4 e4  = *(const float4*)(g_ve + off);
            vs [rr][kq+0] = v4.x; vs [rr][kq+1] = v4.y; vs [rr][kq+2] = v4.z; vs [rr][kq+3] = v4.w;
            ves[rr][kq+0] = e4.x; ves[rr][kq+1] = e4.y; ves[rr][kq+2] = e4.z; ves[rr][kq+3] = e4.w;
        }
        // ---- load probs tile 16x64 ----
        if (tid < 256) {
            int nn = tid >> 4;
            int mq = (tid & 15) << 2;
            float4 p4 = *(const float4*)(g_attn +
                (((long long)(b*NH + h)*NN + n0 + nn))*NEXT + m0 + mq);
            ps[nn][mq+0] = p4.x; ps[nn][mq+1] = p4.y; ps[nn][mq+2] = p4.z; ps[nn][mq+3] = p4.w;
        }
        // ---- compute delta tile 16x64x3 ----
        #pragma unroll
        for (int ph = 0; ph < 2; ph++) {
            int idx = tid + (ph << 9);
            int nn = idx >> 6;          // 0..15
            int mm = idx & 63;
            int n = n0 + nn;
            int m = m0 + mm;
            float px = pos[(b*NN + n)*3 + 0];
            float py = pos[(b*NN + n)*3 + 1];
            float pz = pos[(b*NN + n)*3 + 2];
            float ax, ay, az; bool fm;
            if (m < NN) {
                ax = pos[(b*NN + m)*3 + 0];
                ay = pos[(b*NN + m)*3 + 1];
                az = pos[(b*NN + m)*3 + 2];
                fm = pmask[b*NN + m] != 0;
            } else {
                int me = m - NN;
                ax = epos[(b*NM + me)*3 + 0];
                ay = epos[(b*NM + me)*3 + 1];
                az = epos[(b*NM + me)*3 + 2];
                fm = emask[b*NM + me] != 0;
            }
            float dx = px - ax, dy = py - ay, dz = pz - az;
            float dist = sqrtf(dx*dx + dy*dy + dz*dz);
            bool pn = pmask[b*NN + n] != 0;
            if (pn || fm) dist = 1e6f;
            float inv = 1.f / (dist + 1.f);
            if (pn) inv = 0.f;   // final where(padding_mask, 0, delta)
            dxs[nn][mm] = dx * inv;
            dys[nn][mm] = dy * inv;
            dzs[nn][mm] = dz * inv;
        }
        __syncthreads();

        #pragma unroll
        for (int mm = 0; mm < 64; mm++) {
            float p  = ps[tn][mm];
            float v  = vs [mm][td];
            float ve = ves[mm][td];
            accxo = fmaf(p, ve, accxo);
            float a = p * v;
            accx = fmaf(a, dxs[tn][mm], accx);
            accy = fmaf(a, dys[tn][mm], accy);
            accz = fmaf(a, dzs[tn][mm], accz);
        }
        __syncthreads();
    }

    const int n   = n0 + tn;
    const int col = h*ND + td;
    g_xo[((long long)(b*NN + n))*NE + col] = accxo;
    long long vb = (((long long)(b*NN + n))*3)*NE + col;
    g_vec[vb         ] = accx;
    g_vec[vb +   NE  ] = accy;
    g_vec[vb + 2*NE  ] = accz;
}

// ============================================================================
// launch
// ============================================================================
extern "C" void kernel_launch(void* const* d_in, const int* in_sizes, int n_in,
                              void* d_out, int out_size)
{
    const float* x    = (const float*)d_in[0];
    const float* pos  = (const float*)d_in[1];
    const float* epos = (const float*)d_in[2];
    const float* bias = (const float*)d_in[3];
    const unsigned char* pmask = (const unsigned char*)d_in[4];
    const unsigned char* emask = (const unsigned char*)d_in[5];
    const int*   oidx = (const int*)d_in[6];
    const float* Wq   = (const float*)d_in[7];
    const float* Wk   = (const float*)d_in[8];
    const float* Wv   = (const float*)d_in[9];
    const float* Wve  = (const float*)d_in[10];
    const float* Wo   = (const float*)d_in[11];
    const float* Woe  = (const float*)d_in[12];
    float* out = (float*)d_out;

    float *q, *k, *v, *ve, *xo, *vec;
    cudaGetSymbolAddress((void**)&q,   g_q);
    cudaGetSymbolAddress((void**)&k,   g_k);
    cudaGetSymbolAddress((void**)&v,   g_v);
    cudaGetSymbolAddress((void**)&ve,  g_ve);
    cudaGetSymbolAddress((void**)&xo,  g_xo);
    cudaGetSymbolAddress((void**)&vec, g_vec);

    dim3 gProj(NE/64, (NB*NN)/64);          // 16 x 32
    gemm64<<<gProj, 256>>>(x, Wq,  q,  SCALING_F, 1);
    gemm64<<<gProj, 256>>>(x, Wk,  k,  1.f, 1);
    gemm64<<<gProj, 256>>>(x, Wv,  v,  1.f, 1);
    gemm64<<<gProj, 256>>>(x, Wve, ve, 1.f, 1);

    qk64<<<dim3(NEXT/64, NN/64, NB*NH), 256>>>(bias, oidx, pmask, emask);

    softmax768<<<NB*NH*NN, 256>>>();

    pv_vec<<<dim3(NN/16, NH, NB), 512>>>(pos, epos, oidx, pmask, emask);

    // outputs: xo [B,N,E] first, then vec_out [B,N,3,E]
    gemm64<<<dim3(NE/64, (NB*NN)/64), 256>>>(xo,  Woe, out,                1.f, 0);
    gemm64<<<dim3(NE/64, (NB*NN*3)/64), 256>>>(vec, Wo, out + NB*NN*NE,    1.f, 0);
}

// round 3
// speedup vs baseline: 1.5710x; 1.5710x over previous
#include <cuda_runtime.h>
#include <cuda_bf16.h>
#include <float.h>
#include <math.h>
#include <stdint.h>

// Problem constants
#define NB 8
#define NN 256
#define NM 512
#define NE 1024
#define NH 32
#define ND 32
#define NEXT 768   // N + M

#define SCALING_F 0.17677669529663687f  // 32^-0.5

// ---------------- device scratch (static, allowed) ----------------
static __device__ float g_proj[4LL*2048*1024];          // q,k,v,ve
#define G_Q  (g_proj)
#define G_K  (g_proj + 2097152)
#define G_V  (g_proj + 2*2097152)
#define G_VE (g_proj + 3*2097152)
static __device__ float g_attn[(long long)NB*NH*NN*NEXT];
static __device__ float g_xo [NB*NN*NE];
static __device__ float g_vec[NB*NN*3*NE];
// bf16 split-precision staging
static __device__ __nv_bfloat16 g_ah[6144LL*1024];   // activation hi (max rows 6144)
static __device__ __nv_bfloat16 g_al[6144LL*1024];   // activation lo
static __device__ __nv_bfloat16 g_wh[6LL*1024*1024]; // weights hi (Wq,Wk,Wv,Wve,Woe,Wo)
static __device__ __nv_bfloat16 g_wl[6LL*1024*1024];

// ============================================================================
// helpers
// ============================================================================
__device__ __forceinline__ uint32_t smem_u32(const void* p) {
    uint32_t a;
    asm("{ .reg .u64 t; cvta.to.shared.u64 t, %1; cvt.u32.u64 %0, t; }"
        : "=r"(a) : "l"(p));
    return a;
}
#define CP_ASYNC16(sa, ga) \
    asm volatile("cp.async.cg.shared.global [%0], [%1], 16;\n" :: "r"(sa), "l"(ga))
#define CP_COMMIT() asm volatile("cp.async.commit_group;\n" ::: "memory")
#define CP_WAIT(n)  asm volatile("cp.async.wait_group %0;\n" :: "n"(n) : "memory")

__device__ __forceinline__ void mma16816(float* c, const uint32_t* a, const uint32_t* b) {
    asm volatile(
        "mma.sync.aligned.m16n8k16.row.col.f32.bf16.bf16.f32 "
        "{%0,%1,%2,%3}, {%4,%5,%6,%7}, {%8,%9}, {%0,%1,%2,%3};\n"
        : "+f"(c[0]), "+f"(c[1]), "+f"(c[2]), "+f"(c[3])
        : "r"(a[0]), "r"(a[1]), "r"(a[2]), "r"(a[3]), "r"(b[0]), "r"(b[1]));
}

// ============================================================================
// Split fp32 -> bf16 hi/lo
// ============================================================================
__global__ __launch_bounds__(256) void cvt_split(const float* __restrict__ src,
                                                 __nv_bfloat16* __restrict__ hi,
                                                 __nv_bfloat16* __restrict__ lo,
                                                 int n4)
{
    int i = blockIdx.x * 256 + threadIdx.x;
    if (i >= n4) return;
    float4 v = ((const float4*)src)[i];
    __nv_bfloat16 h[4], l[4];
    h[0] = __float2bfloat16(v.x); l[0] = __float2bfloat16(v.x - __bfloat162float(h[0]));
    h[1] = __float2bfloat16(v.y); l[1] = __float2bfloat16(v.y - __bfloat162float(h[1]));
    h[2] = __float2bfloat16(v.z); l[2] = __float2bfloat16(v.z - __bfloat162float(h[2]));
    h[3] = __float2bfloat16(v.w); l[3] = __float2bfloat16(v.w - __bfloat162float(h[3]));
    ((uint2*)hi)[i] = *(uint2*)h;
    ((uint2*)lo)[i] = *(uint2*)l;
}

// x is [N, B, E]; emit row-major [B*N, E] hi/lo
__global__ __launch_bounds__(256) void cvt_split_x(const float* __restrict__ src,
                                                   __nv_bfloat16* __restrict__ hi,
                                                   __nv_bfloat16* __restrict__ lo)
{
    int i = blockIdx.x * 256 + threadIdx.x;   // quad index
    int r  = i >> 8;
    int e4 = (i & 255) << 2;
    int b = r >> 8, n = r & 255;
    float4 v = *(const float4*)(src + ((long long)n * NB + b) * NE + e4);
    __nv_bfloat16 h[4], l[4];
    h[0] = __float2bfloat16(v.x); l[0] = __float2bfloat16(v.x - __bfloat162float(h[0]));
    h[1] = __float2bfloat16(v.y); l[1] = __float2bfloat16(v.y - __bfloat162float(h[1]));
    h[2] = __float2bfloat16(v.z); l[2] = __float2bfloat16(v.z - __bfloat162float(h[2]));
    h[3] = __float2bfloat16(v.w); l[3] = __float2bfloat16(v.w - __bfloat162float(h[3]));
    ((uint2*)hi)[i] = *(uint2*)h;
    ((uint2*)lo)[i] = *(uint2*)l;
}

// ============================================================================
// Tensor-core (mma.sync bf16) split-precision GEMM: C = alpha * A @ W^T
//   A: [Mrows, 1024] hi/lo, W: [1024, 1024] hi/lo; CTA tile 128x128, K-chunk 32.
//   blockIdx.z selects weight slice (z<<20) and C slice (z<<21); alpha if z==0.
//   Dynamic smem: 2 stages x 4 tiles x 128 rows x 40 bf16 (80B padded stride).
// ============================================================================
#define TILE_ELE 5120          // 128 * 40 bf16 per tile
#define STAGE_ELE 20480        // 4 tiles
#define GSMEM_BYTES 81920

__global__ __launch_bounds__(256, 2) void gemm_mma(const __nv_bfloat16* __restrict__ Ah,
                                                   const __nv_bfloat16* __restrict__ Al,
                                                   const __nv_bfloat16* __restrict__ Bh,
                                                   const __nv_bfloat16* __restrict__ Bl,
                                                   float* __restrict__ C,
                                                   float alpha0)
{
    extern __shared__ __nv_bfloat16 sm[];

    const int tid  = threadIdx.x;
    const int wid  = tid >> 5;
    const int lane = tid & 31;
    const int g    = lane >> 2;   // group (row within 8)
    const int tig  = lane & 3;    // thread-in-group (k word)
    const int row0 = blockIdx.y << 7;
    const int col0 = blockIdx.x << 7;
    const int z    = blockIdx.z;
    Bh += (size_t)z << 20;
    Bl += (size_t)z << 20;
    C  += (size_t)z << 21;
    const float alpha = (z == 0) ? alpha0 : 1.0f;
    const int wm = (wid & 1) << 6;   // 0 / 64
    const int wn = (wid >> 1) << 5;  // 0 / 32 / 64 / 96

    float acc[4][4][4];
    #pragma unroll
    for (int i = 0; i < 4; i++)
        #pragma unroll
        for (int j = 0; j < 4; j++)
            #pragma unroll
            for (int q = 0; q < 4; q++) acc[i][j][q] = 0.f;

    const uint32_t smbase = smem_u32(sm);

    // per-thread cp.async mapping (8 x 16B per chunk)
    // u = tid + t*256 ; tile = u>>9 ; r = (u>>2)&127 ; cu = u&3
    #define LOAD_CHUNK(kc, s)                                                     \
    {                                                                             \
        _Pragma("unroll")                                                         \
        for (int t = 0; t < 8; t++) {                                             \
            int u    = tid + (t << 8);                                            \
            int tile = u >> 9;                                                    \
            int r    = (u >> 2) & 127;                                            \
            int cu   = u & 3;                                                     \
            const __nv_bfloat16* gp;                                              \
            if      (tile == 0) gp = Ah + (size_t)(row0 + r) * 1024;              \
            else if (tile == 1) gp = Al + (size_t)(row0 + r) * 1024;              \
            else if (tile == 2) gp = Bh + (size_t)(col0 + r) * 1024;              \
            else                gp = Bl + (size_t)(col0 + r) * 1024;              \
            gp += (kc) * 32 + cu * 8;                                             \
            uint32_t sa = smbase +                                                \
                (uint32_t)(((s) * STAGE_ELE + tile * TILE_ELE + r * 40 + cu * 8) * 2); \
            CP_ASYNC16(sa, gp);                                                   \
        }                                                                         \
    }

    LOAD_CHUNK(0, 0);
    CP_COMMIT();

    for (int kc = 0; kc < 32; kc++) {
        if (kc + 1 < 32) {
            LOAD_CHUNK(kc + 1, (kc + 1) & 1);
            CP_COMMIT();
            CP_WAIT(1);
        } else {
            CP_WAIT(0);
        }
        __syncthreads();

        const int so = (kc & 1) * STAGE_ELE;
        #pragma unroll
        for (int kk = 0; kk < 2; kk++) {
            const int kw = kk << 3;
            uint32_t ah[4][4], al[4][4], bh[4][2], bl[4][2];
            // fragment loads (32-bit LDS, documented m16n8k16 layout)
            #pragma unroll
            for (int i = 0; i < 4; i++) {
                int rA = wm + (i << 4) + g;
                const __nv_bfloat16* ph = sm + so + 0 * TILE_ELE;
                const __nv_bfloat16* pl = sm + so + 1 * TILE_ELE;
                ah[i][0] = *(const uint32_t*)(ph + (rA    ) * 40 + ((kw + tig    ) << 1));
                ah[i][1] = *(const uint32_t*)(ph + (rA + 8) * 40 + ((kw + tig    ) << 1));
                ah[i][2] = *(const uint32_t*)(ph + (rA    ) * 40 + ((kw + tig + 4) << 1));
                ah[i][3] = *(const uint32_t*)(ph + (rA + 8) * 40 + ((kw + tig + 4) << 1));
                al[i][0] = *(const uint32_t*)(pl + (rA    ) * 40 + ((kw + tig    ) << 1));
                al[i][1] = *(const uint32_t*)(pl + (rA + 8) * 40 + ((kw + tig    ) << 1));
                al[i][2] = *(const uint32_t*)(pl + (rA    ) * 40 + ((kw + tig + 4) << 1));
                al[i][3] = *(const uint32_t*)(pl + (rA + 8) * 40 + ((kw + tig + 4) << 1));
            }
            #pragma unroll
            for (int j = 0; j < 4; j++) {
                int rB = wn + (j << 3) + g;
                const __nv_bfloat16* ph = sm + so + 2 * TILE_ELE;
                const __nv_bfloat16* pl = sm + so + 3 * TILE_ELE;
                bh[j][0] = *(const uint32_t*)(ph + rB * 40 + ((kw + tig    ) << 1));
                bh[j][1] = *(const uint32_t*)(ph + rB * 40 + ((kw + tig + 4) << 1));
                bl[j][0] = *(const uint32_t*)(pl + rB * 40 + ((kw + tig    ) << 1));
                bl[j][1] = *(const uint32_t*)(pl + rB * 40 + ((kw + tig + 4) << 1));
            }
            #pragma unroll
            for (int i = 0; i < 4; i++)
                #pragma unroll
                for (int j = 0; j < 4; j++) {
                    mma16816(acc[i][j], ah[i], bh[j]);
                    mma16816(acc[i][j], ah[i], bl[j]);
                    mma16816(acc[i][j], al[i], bh[j]);
                }
        }
        __syncthreads();
    }

    // epilogue
    #pragma unroll
    for (int i = 0; i < 4; i++) {
        int row = row0 + wm + (i << 4) + g;
        #pragma unroll
        for (int j = 0; j < 4; j++) {
            int col = col0 + wn + (j << 3) + (tig << 1);
            float2 v0, v1;
            v0.x = alpha * acc[i][j][0];
            v0.y = alpha * acc[i][j][1];
            v1.x = alpha * acc[i][j][2];
            v1.y = alpha * acc[i][j][3];
            *(float2*)(C + (size_t)row * 1024 + col)       = v0;
            *(float2*)(C + (size_t)(row + 8) * 1024 + col) = v1;
        }
    }
}

// ============================================================================
// QK^T tile kernel
// ============================================================================
__global__ __launch_bounds__(256) void qk64(const float* __restrict__ bias,
                                            const int*   __restrict__ oidx,
                                            const unsigned char* __restrict__ pmask,
                                            const unsigned char* __restrict__ emask)
{
    __shared__ float qs[32][64];
    __shared__ float ks[32][64];

    const int tid = threadIdx.x;
    const int bh  = blockIdx.z;
    const int b   = bh >> 5;
    const int h   = bh & 31;
    const int n0  = blockIdx.y << 6;
    const int m0  = blockIdx.x << 6;

    #pragma unroll
    for (int ph = 0; ph < 2; ph++) {
        int idx = tid + (ph << 8);
        int rr  = idx >> 3;
        int kq  = (idx & 7) << 2;
        float4 a4 = *(const float4*)(G_Q + ((long long)(b*NN + n0 + rr))*NE + h*ND + kq);
        qs[kq+0][rr] = a4.x; qs[kq+1][rr] = a4.y; qs[kq+2][rr] = a4.z; qs[kq+3][rr] = a4.w;
        int m = m0 + rr;
        int krow = (m < NN) ? m : oidx[b*NM + m - NN];
        float4 k4 = *(const float4*)(G_K + ((long long)(b*NN + krow))*NE + h*ND + kq);
        ks[kq+0][rr] = k4.x; ks[kq+1][rr] = k4.y; ks[kq+2][rr] = k4.z; ks[kq+3][rr] = k4.w;
    }
    __syncthreads();

    const int tn = tid & 15, tm = tid >> 4;
    float acc[4][4];
    #pragma unroll
    for (int i = 0; i < 4; i++)
        #pragma unroll
        for (int j = 0; j < 4; j++) acc[i][j] = 0.f;

    #pragma unroll
    for (int k = 0; k < 32; k++) {
        float4 av = *(const float4*)&qs[k][tm << 2];
        float4 bv = *(const float4*)&ks[k][tn << 2];
        acc[0][0] = fmaf(av.x, bv.x, acc[0][0]);
        acc[0][1] = fmaf(av.x, bv.y, acc[0][1]);
        acc[0][2] = fmaf(av.x, bv.z, acc[0][2]);
        acc[0][3] = fmaf(av.x, bv.w, acc[0][3]);
        acc[1][0] = fmaf(av.y, bv.x, acc[1][0]);
        acc[1][1] = fmaf(av.y, bv.y, acc[1][1]);
        acc[1][2] = fmaf(av.y, bv.z, acc[1][2]);
        acc[1][3] = fmaf(av.y, bv.w, acc[1][3]);
        acc[2][0] = fmaf(av.z, bv.x, acc[2][0]);
        acc[2][1] = fmaf(av.z, bv.y, acc[2][1]);
        acc[2][2] = fmaf(av.z, bv.z, acc[2][2]);
        acc[2][3] = fmaf(av.z, bv.w, acc[2][3]);
        acc[3][0] = fmaf(av.w, bv.x, acc[3][0]);
        acc[3][1] = fmaf(av.w, bv.y, acc[3][1]);
        acc[3][2] = fmaf(av.w, bv.z, acc[3][2]);
        acc[3][3] = fmaf(av.w, bv.w, acc[3][3]);
    }

    const long long base = (long long)(b*NH + h) * NN;
    #pragma unroll
    for (int i = 0; i < 4; i++) {
        int n = n0 + (tm << 2) + i;
        bool pn = pmask[b*NN + n] != 0;
        long long rowoff = (base + n) * NEXT;
        #pragma unroll
        for (int j = 0; j < 4; j++) {
            int m = m0 + (tn << 2) + j;
            bool fm = (m < NN) ? (pmask[b*NN + m] != 0)
                               : (emask[b*NM + m - NN] != 0);
            float v = acc[i][j] + bias[rowoff + m];
            if (pn || fm) v = -FLT_MAX;
            g_attn[rowoff + m] = v;
        }
    }
}

// ============================================================================
// Row softmax over 768 elements (in place)
// ============================================================================
__global__ __launch_bounds__(256) void softmax768()
{
    long long row = blockIdx.x;
    float* p = g_attn + row * NEXT;
    const int tid = threadIdx.x;

    float v0 = p[tid], v1 = p[tid + 256], v2 = p[tid + 512];
    float mx = fmaxf(v0, fmaxf(v1, v2));

    __shared__ float red[8];
    #pragma unroll
    for (int o = 16; o > 0; o >>= 1)
        mx = fmaxf(mx, __shfl_xor_sync(0xffffffffu, mx, o));
    if ((tid & 31) == 0) red[tid >> 5] = mx;
    __syncthreads();
    if (tid < 32) {
        float m2 = (tid < 8) ? red[tid] : -FLT_MAX;
        #pragma unroll
        for (int o = 4; o > 0; o >>= 1)
            m2 = fmaxf(m2, __shfl_xor_sync(0xffffffffu, m2, o));
        if (tid == 0) red[0] = m2;
    }
    __syncthreads();
    mx = red[0];
    __syncthreads();

    float e0 = expf(v0 - mx), e1 = expf(v1 - mx), e2 = expf(v2 - mx);
    float s = e0 + e1 + e2;
    #pragma unroll
    for (int o = 16; o > 0; o >>= 1)
        s += __shfl_xor_sync(0xffffffffu, s, o);
    if ((tid & 31) == 0) red[tid >> 5] = s;
    __syncthreads();
    if (tid < 32) {
        float s2 = (tid < 8) ? red[tid] : 0.f;
        #pragma unroll
        for (int o = 4; o > 0; o >>= 1)
            s2 += __shfl_xor_sync(0xffffffffu, s2, o);
        if (tid == 0) red[0] = s2;
    }
    __syncthreads();
    float inv = 1.f / red[0];

    p[tid]       = e0 * inv;
    p[tid + 256] = e1 * inv;
    p[tid + 512] = e2 * inv;
}

// ============================================================================
// Fused PV + vec kernel
// ============================================================================
__global__ __launch_bounds__(512) void pv_vec(const float* __restrict__ pos,
                                              const float* __restrict__ epos,
                                              const int*   __restrict__ oidx,
                                              const unsigned char* __restrict__ pmask,
                                              const unsigned char* __restrict__ emask)
{
    __shared__ float vs [64][32];
    __shared__ float ves[64][32];
    __shared__ float ps [16][64];
    __shared__ float dxs[16][64];
    __shared__ float dys[16][64];
    __shared__ float dzs[16][64];

    const int b  = blockIdx.z;
    const int h  = blockIdx.y;
    const int n0 = blockIdx.x << 4;
    const int tid = threadIdx.x;
    const int tn = tid >> 5;
    const int td = tid & 31;

    float accxo = 0.f, accx = 0.f, accy = 0.f, accz = 0.f;

    for (int m0 = 0; m0 < NEXT; m0 += 64) {
        {
            int rr = tid >> 3;
            int kq = (tid & 7) << 2;
            int m  = m0 + rr;
            int row = (m < NN) ? m : oidx[b*NM + m - NN];
            long long off = ((long long)(b*NN + row))*NE + h*ND + kq;
            float4 v4  = *(const float4*)(G_V  + off);
            float4 e4  = *(const float4*)(G_VE + off);
            vs [rr][kq+0] = v4.x; vs [rr][kq+1] = v4.y; vs [rr][kq+2] = v4.z; vs [rr][kq+3] = v4.w;
            ves[rr][kq+0] = e4.x; ves[rr][kq+1] = e4.y; ves[rr][kq+2] = e4.z; ves[rr][kq+3] = e4.w;
        }
        if (tid < 256) {
            int nn = tid >> 4;
            int mq = (tid & 15) << 2;
            float4 p4 = *(const float4*)(g_attn +
                (((long long)(b*NH + h)*NN + n0 + nn))*NEXT + m0 + mq);
            ps[nn][mq+0] = p4.x; ps[nn][mq+1] = p4.y; ps[nn][mq+2] = p4.z; ps[nn][mq+3] = p4.w;
        }
        #pragma unroll
        for (int ph = 0; ph < 2; ph++) {
            int idx = tid + (ph << 9);
            int nn = idx >> 6;
            int mm = idx & 63;
            int n = n0 + nn;
            int m = m0 + mm;
            float px = pos[(b*NN + n)*3 + 0];
            float py = pos[(b*NN + n)*3 + 1];
            float pz = pos[(b*NN + n)*3 + 2];
            float ax, ay, az; bool fm;
            if (m < NN) {
                ax = pos[(b*NN + m)*3 + 0];
                ay = pos[(b*NN + m)*3 + 1];
                az = pos[(b*NN + m)*3 + 2];
                fm = pmask[b*NN + m] != 0;
            } else {
                int me = m - NN;
                ax = epos[(b*NM + me)*3 + 0];
                ay = epos[(b*NM + me)*3 + 1];
                az = epos[(b*NM + me)*3 + 2];
                fm = emask[b*NM + me] != 0;
            }
            float dx = px - ax, dy = py - ay, dz = pz - az;
            float dist = sqrtf(dx*dx + dy*dy + dz*dz);
            bool pn = pmask[b*NN + n] != 0;
            if (pn || fm) dist = 1e6f;
            float inv = 1.f / (dist + 1.f);
            if (pn) inv = 0.f;
            dxs[nn][mm] = dx * inv;
            dys[nn][mm] = dy * inv;
            dzs[nn][mm] = dz * inv;
        }
        __syncthreads();

        #pragma unroll
        for (int mm = 0; mm < 64; mm++) {
            float p  = ps[tn][mm];
            float v  = vs [mm][td];
            float ve = ves[mm][td];
            accxo = fmaf(p, ve, accxo);
            float a = p * v;
            accx = fmaf(a, dxs[tn][mm], accx);
            accy = fmaf(a, dys[tn][mm], accy);
            accz = fmaf(a, dzs[tn][mm], accz);
        }
        __syncthreads();
    }

    const int n   = n0 + tn;
    const int col = h*ND + td;
    g_xo[((long long)(b*NN + n))*NE + col] = accxo;
    long long vb = (((long long)(b*NN + n))*3)*NE + col;
    g_vec[vb         ] = accx;
    g_vec[vb +   NE  ] = accy;
    g_vec[vb + 2*NE  ] = accz;
}

// ============================================================================
// launch
// ============================================================================
extern "C" void kernel_launch(void* const* d_in, const int* in_sizes, int n_in,
                              void* d_out, int out_size)
{
    const float* x    = (const float*)d_in[0];
    const float* pos  = (const float*)d_in[1];
    const float* epos = (const float*)d_in[2];
    const float* bias = (const float*)d_in[3];
    const unsigned char* pmask = (const unsigned char*)d_in[4];
    const unsigned char* emask = (const unsigned char*)d_in[5];
    const int*   oidx = (const int*)d_in[6];
    const float* Wq   = (const float*)d_in[7];
    const float* Wk   = (const float*)d_in[8];
    const float* Wv   = (const float*)d_in[9];
    const float* Wve  = (const float*)d_in[10];
    const float* Wo   = (const float*)d_in[11];
    const float* Woe  = (const float*)d_in[12];
    float* out = (float*)d_out;

    float *proj, *xo, *vec;
    __nv_bfloat16 *ah, *al, *wh, *wl;
    cudaGetSymbolAddress((void**)&proj, g_proj);
    cudaGetSymbolAddress((void**)&xo,   g_xo);
    cudaGetSymbolAddress((void**)&vec,  g_vec);
    cudaGetSymbolAddress((void**)&ah,   g_ah);
    cudaGetSymbolAddress((void**)&al,   g_al);
    cudaGetSymbolAddress((void**)&wh,   g_wh);
    cudaGetSymbolAddress((void**)&wl,   g_wl);

    static int s_attr_done = 0;
    if (!s_attr_done) {
        cudaFuncSetAttribute(gemm_mma, cudaFuncAttributeMaxDynamicSharedMemorySize,
                             GSMEM_BYTES);
        s_attr_done = 1;
    }

    const int WSZ = 1024 * 1024;

    // 1) split-convert x (permuted) and the 6 weights to bf16 hi/lo
    cvt_split_x<<<2048, 256>>>(x, ah, al);
    cvt_split<<<1024, 256>>>(Wq,  wh + 0*WSZ, wl + 0*WSZ, WSZ/4);
    cvt_split<<<1024, 256>>>(Wk,  wh + 1*WSZ, wl + 1*WSZ, WSZ/4);
    cvt_split<<<1024, 256>>>(Wv,  wh + 2*WSZ, wl + 2*WSZ, WSZ/4);
    cvt_split<<<1024, 256>>>(Wve, wh + 3*WSZ, wl + 3*WSZ, WSZ/4);
    cvt_split<<<1024, 256>>>(Woe, wh + 4*WSZ, wl + 4*WSZ, WSZ/4);
    cvt_split<<<1024, 256>>>(Wo,  wh + 5*WSZ, wl + 5*WSZ, WSZ/4);

    // 2) four projections in one tensor-core launch
    gemm_mma<<<dim3(8, 16, 4), 256, GSMEM_BYTES>>>(ah, al, wh, wl, proj, SCALING_F);

    // 3) attention
    qk64<<<dim3(NEXT/64, NN/64, NB*NH), 256>>>(bias, oidx, pmask, emask);
    softmax768<<<NB*NH*NN, 256>>>();
    pv_vec<<<dim3(NN/16, NH, NB), 512>>>(pos, epos, oidx, pmask, emask);

    // 4) output GEMMs
    cvt_split<<<2048, 256>>>(xo, ah, al, (NB*NN*NE)/4);
    gemm_mma<<<dim3(8, 16, 1), 256, GSMEM_BYTES>>>(ah, al, wh + 4*WSZ, wl + 4*WSZ,
                                                   out, 1.0f);

    cvt_split<<<6144, 256>>>(vec, ah, al, (NB*NN*3*NE)/4);
    gemm_mma<<<dim3(8, 48, 1), 256, GSMEM_BYTES>>>(ah, al, wh + 5*WSZ, wl + 5*WSZ,
                                                   out + NB*NN*NE, 1.0f);
}

// round 4
// speedup vs baseline: 2.4416x; 1.5542x over previous
#include <cuda_runtime.h>
#include <cuda_bf16.h>
#include <float.h>
#include <math.h>
#include <stdint.h>

// Problem constants
#define NB 8
#define NN 256
#define NM 512
#define NE 1024
#define NH 32
#define ND 32
#define NEXT 768   // N + M

#define SCALING_F 0.17677669529663687f  // 32^-0.5

// ---------------- device scratch ----------------
static __device__ float g_attn[(long long)NB*NH*NN*NEXT];   // probs (fp32)
static __device__ float g_xo [NB*NN*NE];
static __device__ float g_vec[NB*NN*3*NE];
// bf16 split staging
static __device__ __nv_bfloat16 g_ah[6144LL*1024];   // activation hi
static __device__ __nv_bfloat16 g_al[6144LL*1024];   // activation lo
static __device__ __nv_bfloat16 g_wh[6LL*1024*1024]; // weights hi
static __device__ __nv_bfloat16 g_wl[6LL*1024*1024];
// projections q,k,v,ve in bf16 hi/lo ([b*n, e] row-major, 2M elements each)
static __device__ __nv_bfloat16 g_projh[4LL*2048*1024];
static __device__ __nv_bfloat16 g_projl[4LL*2048*1024];
#define PSZ 2097152

// ============================================================================
// helpers
// ============================================================================
__device__ __forceinline__ uint32_t smem_u32(const void* p) {
    uint32_t a;
    asm("{ .reg .u64 t; cvta.to.shared.u64 t, %1; cvt.u32.u64 %0, t; }"
        : "=r"(a) : "l"(p));
    return a;
}
#define CP_ASYNC16(sa, ga) \
    asm volatile("cp.async.cg.shared.global [%0], [%1], 16;\n" :: "r"(sa), "l"(ga))
#define CP_COMMIT() asm volatile("cp.async.commit_group;\n" ::: "memory")
#define CP_WAIT(n)  asm volatile("cp.async.wait_group %0;\n" :: "n"(n) : "memory")

__device__ __forceinline__ void mma16816(float* c, const uint32_t* a, const uint32_t* b) {
    asm volatile(
        "mma.sync.aligned.m16n8k16.row.col.f32.bf16.bf16.f32 "
        "{%0,%1,%2,%3}, {%4,%5,%6,%7}, {%8,%9}, {%0,%1,%2,%3};\n"
        : "+f"(c[0]), "+f"(c[1]), "+f"(c[2]), "+f"(c[3])
        : "r"(a[0]), "r"(a[1]), "r"(a[2]), "r"(a[3]), "r"(b[0]), "r"(b[1]));
}

// split two floats into packed bf16 hi/lo words
__device__ __forceinline__ void split2(float a, float b, uint32_t& hi, uint32_t& lo) {
    __nv_bfloat16 h0 = __float2bfloat16(a);
    __nv_bfloat16 h1 = __float2bfloat16(b);
    __nv_bfloat16 l0 = __float2bfloat16(a - __bfloat162float(h0));
    __nv_bfloat16 l1 = __float2bfloat16(b - __bfloat162float(h1));
    __nv_bfloat162 H; H.x = h0; H.y = h1;
    __nv_bfloat162 L; L.x = l0; L.y = l1;
    hi = *(uint32_t*)&H;
    lo = *(uint32_t*)&L;
}

// ============================================================================
// Split fp32 -> bf16 hi/lo converters
// ============================================================================
__global__ __launch_bounds__(256) void cvt_split(const float* __restrict__ src,
                                                 __nv_bfloat16* __restrict__ hi,
                                                 __nv_bfloat16* __restrict__ lo,
                                                 int n4)
{
    int i = blockIdx.x * 256 + threadIdx.x;
    if (i >= n4) return;
    float4 v = ((const float4*)src)[i];
    uint32_t h0, l0, h1, l1;
    split2(v.x, v.y, h0, l0);
    split2(v.z, v.w, h1, l1);
    uint2 H = make_uint2(h0, h1), L = make_uint2(l0, l1);
    ((uint2*)hi)[i] = H;
    ((uint2*)lo)[i] = L;
}

__global__ __launch_bounds__(256) void cvt_split_x(const float* __restrict__ src,
                                                   __nv_bfloat16* __restrict__ hi,
                                                   __nv_bfloat16* __restrict__ lo)
{
    int i = blockIdx.x * 256 + threadIdx.x;
    int r  = i >> 8;
    int e4 = (i & 255) << 2;
    int b = r >> 8, n = r & 255;
    float4 v = *(const float4*)(src + ((long long)n * NB + b) * NE + e4);
    uint32_t h0, l0, h1, l1;
    split2(v.x, v.y, h0, l0);
    split2(v.z, v.w, h1, l1);
    ((uint2*)hi)[i] = make_uint2(h0, h1);
    ((uint2*)lo)[i] = make_uint2(l0, l1);
}

// ============================================================================
// Tensor-core split-precision GEMM: C = alpha * A @ W^T
//   mode 0: write fp32 to C.  mode 1: write bf16 hi/lo to Ch/Cl.
// ============================================================================
#define TILE_ELE 5120
#define STAGE_ELE 20480
#define GSMEM_BYTES 81920

__global__ __launch_bounds__(256, 2) void gemm_mma(const __nv_bfloat16* __restrict__ Ah,
                                                   const __nv_bfloat16* __restrict__ Al,
                                                   const __nv_bfloat16* __restrict__ Bh,
                                                   const __nv_bfloat16* __restrict__ Bl,
                                                   float* __restrict__ C,
                                                   __nv_bfloat16* __restrict__ Ch,
                                                   __nv_bfloat16* __restrict__ Cl,
                                                   float alpha0, int mode)
{
    extern __shared__ __nv_bfloat16 sm[];

    const int tid  = threadIdx.x;
    const int wid  = tid >> 5;
    const int lane = tid & 31;
    const int g    = lane >> 2;
    const int tig  = lane & 3;
    const int row0 = blockIdx.y << 7;
    const int col0 = blockIdx.x << 7;
    const int z    = blockIdx.z;
    Bh += (size_t)z << 20;
    Bl += (size_t)z << 20;
    if (mode == 0) C += (size_t)z << 21;
    else { Ch += (size_t)z << 21; Cl += (size_t)z << 21; }
    const float alpha = (z == 0) ? alpha0 : 1.0f;
    const int wm = (wid & 1) << 6;
    const int wn = (wid >> 1) << 5;

    float acc[4][4][4];
    #pragma unroll
    for (int i = 0; i < 4; i++)
        #pragma unroll
        for (int j = 0; j < 4; j++)
            #pragma unroll
            for (int q = 0; q < 4; q++) acc[i][j][q] = 0.f;

    const uint32_t smbase = smem_u32(sm);

    #define LOAD_CHUNK(kc, s)                                                     \
    {                                                                             \
        _Pragma("unroll")                                                         \
        for (int t = 0; t < 8; t++) {                                             \
            int u    = tid + (t << 8);                                            \
            int tile = u >> 9;                                                    \
            int r    = (u >> 2) & 127;                                            \
            int cu   = u & 3;                                                     \
            const __nv_bfloat16* gp;                                              \
            if      (tile == 0) gp = Ah + (size_t)(row0 + r) * 1024;              \
            else if (tile == 1) gp = Al + (size_t)(row0 + r) * 1024;              \
            else if (tile == 2) gp = Bh + (size_t)(col0 + r) * 1024;              \
            else                gp = Bl + (size_t)(col0 + r) * 1024;              \
            gp += (kc) * 32 + cu * 8;                                             \
            uint32_t sa = smbase +                                                \
                (uint32_t)(((s) * STAGE_ELE + tile * TILE_ELE + r * 40 + cu * 8) * 2); \
            CP_ASYNC16(sa, gp);                                                   \
        }                                                                         \
    }

    LOAD_CHUNK(0, 0);
    CP_COMMIT();

    for (int kc = 0; kc < 32; kc++) {
        if (kc + 1 < 32) {
            LOAD_CHUNK(kc + 1, (kc + 1) & 1);
            CP_COMMIT();
            CP_WAIT(1);
        } else {
            CP_WAIT(0);
        }
        __syncthreads();

        const int so = (kc & 1) * STAGE_ELE;
        #pragma unroll
        for (int kk = 0; kk < 2; kk++) {
            const int kw = kk << 3;
            uint32_t ah[4][4], al[4][4], bh[4][2], bl[4][2];
            #pragma unroll
            for (int i = 0; i < 4; i++) {
                int rA = wm + (i << 4) + g;
                const __nv_bfloat16* ph = sm + so + 0 * TILE_ELE;
                const __nv_bfloat16* pl = sm + so + 1 * TILE_ELE;
                ah[i][0] = *(const uint32_t*)(ph + (rA    ) * 40 + ((kw + tig    ) << 1));
                ah[i][1] = *(const uint32_t*)(ph + (rA + 8) * 40 + ((kw + tig    ) << 1));
                ah[i][2] = *(const uint32_t*)(ph + (rA    ) * 40 + ((kw + tig + 4) << 1));
                ah[i][3] = *(const uint32_t*)(ph + (rA + 8) * 40 + ((kw + tig + 4) << 1));
                al[i][0] = *(const uint32_t*)(pl + (rA    ) * 40 + ((kw + tig    ) << 1));
                al[i][1] = *(const uint32_t*)(pl + (rA + 8) * 40 + ((kw + tig    ) << 1));
                al[i][2] = *(const uint32_t*)(pl + (rA    ) * 40 + ((kw + tig + 4) << 1));
                al[i][3] = *(const uint32_t*)(pl + (rA + 8) * 40 + ((kw + tig + 4) << 1));
            }
            #pragma unroll
            for (int j = 0; j < 4; j++) {
                int rB = wn + (j << 3) + g;
                const __nv_bfloat16* ph = sm + so + 2 * TILE_ELE;
                const __nv_bfloat16* pl = sm + so + 3 * TILE_ELE;
                bh[j][0] = *(const uint32_t*)(ph + rB * 40 + ((kw + tig    ) << 1));
                bh[j][1] = *(const uint32_t*)(ph + rB * 40 + ((kw + tig + 4) << 1));
                bl[j][0] = *(const uint32_t*)(pl + rB * 40 + ((kw + tig    ) << 1));
                bl[j][1] = *(const uint32_t*)(pl + rB * 40 + ((kw + tig + 4) << 1));
            }
            #pragma unroll
            for (int i = 0; i < 4; i++)
                #pragma unroll
                for (int j = 0; j < 4; j++) {
                    mma16816(acc[i][j], ah[i], bh[j]);
                    mma16816(acc[i][j], ah[i], bl[j]);
                    mma16816(acc[i][j], al[i], bh[j]);
                }
        }
        __syncthreads();
    }

    // epilogue
    #pragma unroll
    for (int i = 0; i < 4; i++) {
        int row = row0 + wm + (i << 4) + g;
        #pragma unroll
        for (int j = 0; j < 4; j++) {
            int col = col0 + wn + (j << 3) + (tig << 1);
            float v0 = alpha * acc[i][j][0];
            float v1 = alpha * acc[i][j][1];
            float v2 = alpha * acc[i][j][2];
            float v3 = alpha * acc[i][j][3];
            if (mode == 0) {
                *(float2*)(C + (size_t)row * 1024 + col)       = make_float2(v0, v1);
                *(float2*)(C + (size_t)(row + 8) * 1024 + col) = make_float2(v2, v3);
            } else {
                uint32_t h0, l0, h1, l1;
                split2(v0, v1, h0, l0);
                split2(v2, v3, h1, l1);
                *(uint32_t*)(Ch + (size_t)row * 1024 + col)       = h0;
                *(uint32_t*)(Cl + (size_t)row * 1024 + col)       = l0;
                *(uint32_t*)(Ch + (size_t)(row + 8) * 1024 + col) = h1;
                *(uint32_t*)(Cl + (size_t)(row + 8) * 1024 + col) = l1;
            }
        }
    }
}

// ============================================================================
// Fused QK^T (split bf16 HMMA) + bias + mask + softmax.
// Block = (b,h, 64-row n-tile). Logits row-block in smem (stride 772 floats).
// ============================================================================
#define LSTRIDE 772
#define QK_SMEM 218112   // 64*772*4 + 4*64*40*2

__global__ __launch_bounds__(256) void qk_softmax(const float* __restrict__ bias,
                                                  const int*   __restrict__ oidx,
                                                  const unsigned char* __restrict__ pmask,
                                                  const unsigned char* __restrict__ emask,
                                                  const __nv_bfloat16* __restrict__ qh_g,
                                                  const __nv_bfloat16* __restrict__ ql_g,
                                                  const __nv_bfloat16* __restrict__ kh_g,
                                                  const __nv_bfloat16* __restrict__ kl_g)
{
    extern __shared__ char sraw[];
    float* logits = (float*)sraw;
    __nv_bfloat16* sq = (__nv_bfloat16*)(sraw + 64 * LSTRIDE * 4);
    __nv_bfloat16* sqh = sq;
    __nv_bfloat16* sql = sq + 2560;
    __nv_bfloat16* skh = sq + 5120;
    __nv_bfloat16* skl = sq + 7680;

    const int tid  = threadIdx.x;
    const int wid  = tid >> 5;
    const int lane = tid & 31;
    const int g    = lane >> 2;
    const int tig  = lane & 3;
    const int bh   = blockIdx.y;
    const int b    = bh >> 5;
    const int h    = bh & 31;
    const int n0   = blockIdx.x << 6;

    // load q tile (64 x 32, hi/lo)
    {
        int r = tid >> 2, c = (tid & 3) << 3;
        size_t off = (size_t)(b * NN + n0 + r) * NE + h * ND + c;
        *(uint4*)(sqh + r * 40 + c) = *(const uint4*)(qh_g + off);
        *(uint4*)(sql + r * 40 + c) = *(const uint4*)(ql_g + off);
    }

    const int wn = (wid & 1) << 5;    // 0/32
    const int wm = (wid >> 1) << 4;   // 0,16,32,48

    for (int m0 = 0; m0 < NEXT; m0 += 64) {
        __syncthreads();
        // load k tile (gathered)
        {
            int r = tid >> 2, c = (tid & 3) << 3;
            int m = m0 + r;
            int row = (m < NN) ? m : oidx[b * NM + m - NN];
            size_t off = (size_t)(b * NN + row) * NE + h * ND + c;
            *(uint4*)(skh + r * 40 + c) = *(const uint4*)(kh_g + off);
            *(uint4*)(skl + r * 40 + c) = *(const uint4*)(kl_g + off);
        }
        __syncthreads();

        float acc[2][2][4];
        #pragma unroll
        for (int i = 0; i < 2; i++)
            #pragma unroll
            for (int j = 0; j < 2; j++)
                #pragma unroll
                for (int q = 0; q < 4; q++) acc[i][j][q] = 0.f;

        #pragma unroll
        for (int kk = 0; kk < 2; kk++) {
            const int kw = kk << 3;
            uint32_t ah[2][4], al[2][4], bhf[2][2], blf[2][2];
            #pragma unroll
            for (int i = 0; i < 2; i++) {
                int rA = wn + (i << 4) + g;
                ah[i][0] = *(const uint32_t*)(sqh + (rA    ) * 40 + ((kw + tig    ) << 1));
                ah[i][1] = *(const uint32_t*)(sqh + (rA + 8) * 40 + ((kw + tig    ) << 1));
                ah[i][2] = *(const uint32_t*)(sqh + (rA    ) * 40 + ((kw + tig + 4) << 1));
                ah[i][3] = *(const uint32_t*)(sqh + (rA + 8) * 40 + ((kw + tig + 4) << 1));
                al[i][0] = *(const uint32_t*)(sql + (rA    ) * 40 + ((kw + tig    ) << 1));
                al[i][1] = *(const uint32_t*)(sql + (rA + 8) * 40 + ((kw + tig    ) << 1));
                al[i][2] = *(const uint32_t*)(sql + (rA    ) * 40 + ((kw + tig + 4) << 1));
                al[i][3] = *(const uint32_t*)(sql + (rA + 8) * 40 + ((kw + tig + 4) << 1));
            }
            #pragma unroll
            for (int j = 0; j < 2; j++) {
                int rB = wm + (j << 3) + g;
                bhf[j][0] = *(const uint32_t*)(skh + rB * 40 + ((kw + tig    ) << 1));
                bhf[j][1] = *(const uint32_t*)(skh + rB * 40 + ((kw + tig + 4) << 1));
                blf[j][0] = *(const uint32_t*)(skl + rB * 40 + ((kw + tig    ) << 1));
                blf[j][1] = *(const uint32_t*)(skl + rB * 40 + ((kw + tig + 4) << 1));
            }
            #pragma unroll
            for (int i = 0; i < 2; i++)
                #pragma unroll
                for (int j = 0; j < 2; j++) {
                    mma16816(acc[i][j], ah[i], bhf[j]);
                    mma16816(acc[i][j], ah[i], blf[j]);
                    mma16816(acc[i][j], al[i], bhf[j]);
                }
        }

        // store to logits smem
        #pragma unroll
        for (int i = 0; i < 2; i++) {
            int row = wn + (i << 4) + g;
            #pragma unroll
            for (int j = 0; j < 2; j++) {
                int col = m0 + wm + (j << 3) + (tig << 1);
                *(float2*)&logits[row * LSTRIDE + col]       = make_float2(acc[i][j][0], acc[i][j][1]);
                *(float2*)&logits[(row + 8) * LSTRIDE + col] = make_float2(acc[i][j][2], acc[i][j][3]);
            }
        }
    }
    __syncthreads();

    // softmax: warp handles rows wid, wid+8, ..., wid+56
    for (int rr = wid; rr < 64; rr += 8) {
        int n = n0 + rr;
        bool pn = pmask[b * NN + n] != 0;
        const float* lrow = logits + rr * LSTRIDE;
        long long goff = (((long long)(b * NH + h)) * NN + n) * NEXT;

        float val[24];
        float mx = -FLT_MAX;
        #pragma unroll
        for (int t = 0; t < 24; t++) {
            int m = lane + (t << 5);
            bool fm = (m < NN) ? (pmask[b * NN + m] != 0)
                               : (emask[b * NM + m - NN] != 0);
            float v = lrow[m] + bias[goff + m];
            if (pn || fm) v = -FLT_MAX;
            val[t] = v;
            mx = fmaxf(mx, v);
        }
        #pragma unroll
        for (int o = 16; o > 0; o >>= 1)
            mx = fmaxf(mx, __shfl_xor_sync(0xffffffffu, mx, o));
        float s = 0.f;
        #pragma unroll
        for (int t = 0; t < 24; t++) {
            val[t] = expf(val[t] - mx);
            s += val[t];
        }
        #pragma unroll
        for (int o = 16; o > 0; o >>= 1)
            s += __shfl_xor_sync(0xffffffffu, s, o);
        float inv = 1.f / s;
        #pragma unroll
        for (int t = 0; t < 24; t++)
            g_attn[goff + lane + (t << 5)] = val[t] * inv;
    }
}

// ============================================================================
// Fused PV + vec with split-bf16 HMMA.
//   xo  = P @ VE ;  vec_c = (P .* delta_c) @ V   (c = x,y,z)
// Block = (b,h, 64-row n-tile); m tiled by 64.
// smem: 8 A-mats (P,Pdx,Pdy,Pdz hi/lo) 64x72 bf16 + 4 B-mats (veT,vT hi/lo) 32x72.
// ============================================================================
#define PV_A    4608         // 64*72 elements per A mat
#define PV_VB   36864        // 8*4608
#define PV_B    2304         // 32*72 per B mat
#define PV_SMEM 92160        // (36864 + 4*2304)*2 bytes

__global__ __launch_bounds__(256, 2) void pv_mma(const float* __restrict__ pos,
                                                 const float* __restrict__ epos,
                                                 const int*   __restrict__ oidx,
                                                 const unsigned char* __restrict__ pmask,
                                                 const unsigned char* __restrict__ emask,
                                                 const __nv_bfloat16* __restrict__ vh_g,
                                                 const __nv_bfloat16* __restrict__ vl_g,
                                                 const __nv_bfloat16* __restrict__ veh_g,
                                                 const __nv_bfloat16* __restrict__ vel_g)
{
    extern __shared__ __nv_bfloat16 sp[];

    const int tid  = threadIdx.x;
    const int wid  = tid >> 5;
    const int lane = tid & 31;
    const int g    = lane >> 2;
    const int tig  = lane & 3;
    const int b    = blockIdx.z;
    const int h    = blockIdx.y;
    const int n0   = blockIdx.x << 6;

    const int rowblk = (wid & 3) << 4;   // 0,16,32,48
    const int pair   = wid >> 2;         // 0: (xo, vx)  1: (vy, vz)

    // A mat smem offsets for this warp's two outputs
    const __nv_bfloat16* A0h = sp + ((pair == 0) ? 0 : 4) * PV_A;
    const __nv_bfloat16* A0l = A0h + PV_A;
    const __nv_bfloat16* A1h = sp + ((pair == 0) ? 2 : 6) * PV_A;
    const __nv_bfloat16* A1l = A1h + PV_A;
    const __nv_bfloat16* VEh = sp + PV_VB;
    const __nv_bfloat16* VEl = VEh + PV_B;
    const __nv_bfloat16* Vh  = VEh + 2 * PV_B;
    const __nv_bfloat16* Vl  = VEh + 3 * PV_B;
    const __nv_bfloat16* B0h = (pair == 0) ? VEh : Vh;
    const __nv_bfloat16* B0l = (pair == 0) ? VEl : Vl;
    const __nv_bfloat16* B1h = Vh;
    const __nv_bfloat16* B1l = Vl;

    float acc0[4][4], acc1[4][4];
    #pragma unroll
    for (int j = 0; j < 4; j++)
        #pragma unroll
        for (int q = 0; q < 4; q++) { acc0[j][q] = 0.f; acc1[j][q] = 0.f; }

    // phase-1 thread mapping
    const int p_n  = tid >> 2;          // 0..63
    const int p_mb = (tid & 3) << 4;    // 0,16,32,48
    const float pxn = pos[(b * NN + n0 + p_n) * 3 + 0];
    const float pyn = pos[(b * NN + n0 + p_n) * 3 + 1];
    const float pzn = pos[(b * NN + n0 + p_n) * 3 + 2];
    const bool  pnn = pmask[b * NN + n0 + p_n] != 0;

    for (int m0 = 0; m0 < NEXT; m0 += 64) {
        __syncthreads();
        // ---- phase 1a: P tile + delta -> 4 scaled A mats, split hi/lo ----
        {
            const float* prow = g_attn +
                (((long long)(b * NH + h)) * NN + n0 + p_n) * NEXT + m0 + p_mb;
            float P[16];
            *(float4*)(P + 0)  = *(const float4*)(prow + 0);
            *(float4*)(P + 4)  = *(const float4*)(prow + 4);
            *(float4*)(P + 8)  = *(const float4*)(prow + 8);
            *(float4*)(P + 12) = *(const float4*)(prow + 12);

            float pdx[16], pdy[16], pdz[16];
            #pragma unroll
            for (int q = 0; q < 16; q++) {
                int m = m0 + p_mb + q;
                float ax, ay, az; bool fm;
                if (m < NN) {
                    const float* pp = pos + (b * NN + m) * 3;
                    ax = pp[0]; ay = pp[1]; az = pp[2];
                    fm = pmask[b * NN + m] != 0;
                } else {
                    const float* pp = epos + (b * NM + m - NN) * 3;
                    ax = pp[0]; ay = pp[1]; az = pp[2];
                    fm = emask[b * NM + m - NN] != 0;
                }
                float dx = pxn - ax, dy = pyn - ay, dz = pzn - az;
                float dist = sqrtf(dx * dx + dy * dy + dz * dz);
                if (pnn || fm) dist = 1e6f;
                float inv = 1.f / (dist + 1.f);
                if (pnn) inv = 0.f;
                float Pv = P[q];
                pdx[q] = Pv * dx * inv;
                pdy[q] = Pv * dy * inv;
                pdz[q] = Pv * dz * inv;
            }
            int base = p_n * 72 + p_mb;
            #pragma unroll
            for (int qp = 0; qp < 8; qp++) {
                uint32_t hi, lo;
                split2(P[2*qp], P[2*qp+1], hi, lo);
                *(uint32_t*)(sp + 0 * PV_A + base + 2*qp) = hi;
                *(uint32_t*)(sp + 1 * PV_A + base + 2*qp) = lo;
                split2(pdx[2*qp], pdx[2*qp+1], hi, lo);
                *(uint32_t*)(sp + 2 * PV_A + base + 2*qp) = hi;
                *(uint32_t*)(sp + 3 * PV_A + base + 2*qp) = lo;
                split2(pdy[2*qp], pdy[2*qp+1], hi, lo);
                *(uint32_t*)(sp + 4 * PV_A + base + 2*qp) = hi;
                *(uint32_t*)(sp + 5 * PV_A + base + 2*qp) = lo;
                split2(pdz[2*qp], pdz[2*qp+1], hi, lo);
                *(uint32_t*)(sp + 6 * PV_A + base + 2*qp) = hi;
                *(uint32_t*)(sp + 7 * PV_A + base + 2*qp) = lo;
            }
        }
        // ---- phase 1b: v / ve tiles transposed into B mats ----
        {
            int d  = tid & 31;
            int mq = tid >> 5;     // 0..7
            #pragma unroll
            for (int s = 0; s < 8; s++) {
                int m = (mq << 3) + s;
                int mg = m0 + m;
                int row = (mg < NN) ? mg : oidx[b * NM + mg - NN];
                size_t off = (size_t)(b * NN + row) * NE + h * ND + d;
                ((__nv_bfloat16*)VEh)[d * 72 + m] = veh_g[off];
                ((__nv_bfloat16*)VEl)[d * 72 + m] = vel_g[off];
                ((__nv_bfloat16*)Vh )[d * 72 + m] = vh_g [off];
                ((__nv_bfloat16*)Vl )[d * 72 + m] = vl_g [off];
            }
        }
        __syncthreads();

        // ---- phase 2: MMAs ----
        #pragma unroll
        for (int o = 0; o < 2; o++) {
            const __nv_bfloat16* Amh = o ? A1h : A0h;
            const __nv_bfloat16* Aml = o ? A1l : A0l;
            const __nv_bfloat16* Bmh = o ? B1h : B0h;
            const __nv_bfloat16* Bml = o ? B1l : B0l;
            float (*acc)[4] = o ? acc1 : acc0;
            #pragma unroll
            for (int kk = 0; kk < 4; kk++) {
                const int kp = (kk << 3) + tig;
                uint32_t ah[4], al[4];
                int ra = rowblk + g;
                ah[0] = *(const uint32_t*)(Amh + (ra    ) * 72 + (kp << 1));
                ah[1] = *(const uint32_t*)(Amh + (ra + 8) * 72 + (kp << 1));
                ah[2] = *(const uint32_t*)(Amh + (ra    ) * 72 + ((kp + 4) << 1));
                ah[3] = *(const uint32_t*)(Amh + (ra + 8) * 72 + ((kp + 4) << 1));
                al[0] = *(const uint32_t*)(Aml + (ra    ) * 72 + (kp << 1));
                al[1] = *(const uint32_t*)(Aml + (ra + 8) * 72 + (kp << 1));
                al[2] = *(const uint32_t*)(Aml + (ra    ) * 72 + ((kp + 4) << 1));
                al[3] = *(const uint32_t*)(Aml + (ra + 8) * 72 + ((kp + 4) << 1));
                #pragma unroll
                for (int j = 0; j < 4; j++) {
                    int rb = (j << 3) + g;
                    uint32_t bh[2], bl[2];
                    bh[0] = *(const uint32_t*)(Bmh + rb * 72 + (kp << 1));
                    bh[1] = *(const uint32_t*)(Bmh + rb * 72 + ((kp + 4) << 1));
                    bl[0] = *(const uint32_t*)(Bml + rb * 72 + (kp << 1));
                    bl[1] = *(const uint32_t*)(Bml + rb * 72 + ((kp + 4) << 1));
                    mma16816(acc[j], ah, bh);
                    mma16816(acc[j], ah, bl);
                    mma16816(acc[j], al, bh);
                }
            }
        }
    }

    // ---- epilogue ----
    const int r0 = n0 + rowblk + g;
    #pragma unroll
    for (int j = 0; j < 4; j++) {
        int col = h * ND + (j << 3) + (tig << 1);
        if (pair == 0) {
            // xo
            *(float2*)(g_xo + (size_t)(b * NN + r0) * NE + col)     = make_float2(acc0[j][0], acc0[j][1]);
            *(float2*)(g_xo + (size_t)(b * NN + r0 + 8) * NE + col) = make_float2(acc0[j][2], acc0[j][3]);
            // vec c=0
            *(float2*)(g_vec + ((size_t)(b * NN + r0) * 3 + 0) * NE + col)     = make_float2(acc1[j][0], acc1[j][1]);
            *(float2*)(g_vec + ((size_t)(b * NN + r0 + 8) * 3 + 0) * NE + col) = make_float2(acc1[j][2], acc1[j][3]);
        } else {
            // vec c=1
            *(float2*)(g_vec + ((size_t)(b * NN + r0) * 3 + 1) * NE + col)     = make_float2(acc0[j][0], acc0[j][1]);
            *(float2*)(g_vec + ((size_t)(b * NN + r0 + 8) * 3 + 1) * NE + col) = make_float2(acc0[j][2], acc0[j][3]);
            // vec c=2
            *(float2*)(g_vec + ((size_t)(b * NN + r0) * 3 + 2) * NE + col)     = make_float2(acc1[j][0], acc1[j][1]);
            *(float2*)(g_vec + ((size_t)(b * NN + r0 + 8) * 3 + 2) * NE + col) = make_float2(acc1[j][2], acc1[j][3]);
        }
    }
}

// ============================================================================
// launch
// ============================================================================
extern "C" void kernel_launch(void* const* d_in, const int* in_sizes, int n_in,
                              void* d_out, int out_size)
{
    const float* x    = (const float*)d_in[0];
    const float* pos  = (const float*)d_in[1];
    const float* epos = (const float*)d_in[2];
    const float* bias = (const float*)d_in[3];
    const unsigned char* pmask = (const unsigned char*)d_in[4];
    const unsigned char* emask = (const unsigned char*)d_in[5];
    const int*   oidx = (const int*)d_in[6];
    const float* Wq   = (const float*)d_in[7];
    const float* Wk   = (const float*)d_in[8];
    const float* Wv   = (const float*)d_in[9];
    const float* Wve  = (const float*)d_in[10];
    const float* Wo   = (const float*)d_in[11];
    const float* Woe  = (const float*)d_in[12];
    float* out = (float*)d_out;

    float *xo, *vec;
    __nv_bfloat16 *ah, *al, *wh, *wl, *ph, *pl;
    cudaGetSymbolAddress((void**)&xo,  g_xo);
    cudaGetSymbolAddress((void**)&vec, g_vec);
    cudaGetSymbolAddress((void**)&ah,  g_ah);
    cudaGetSymbolAddress((void**)&al,  g_al);
    cudaGetSymbolAddress((void**)&wh,  g_wh);
    cudaGetSymbolAddress((void**)&wl,  g_wl);
    cudaGetSymbolAddress((void**)&ph,  g_projh);
    cudaGetSymbolAddress((void**)&pl,  g_projl);

    cudaFuncSetAttribute(gemm_mma,   cudaFuncAttributeMaxDynamicSharedMemorySize, GSMEM_BYTES);
    cudaFuncSetAttribute(qk_softmax, cudaFuncAttributeMaxDynamicSharedMemorySize, QK_SMEM);
    cudaFuncSetAttribute(pv_mma,     cudaFuncAttributeMaxDynamicSharedMemorySize, PV_SMEM);

    const int WSZ = 1024 * 1024;

    // 1) split-convert x and weights
    cvt_split_x<<<2048, 256>>>(x, ah, al);
    cvt_split<<<1024, 256>>>(Wq,  wh + 0*WSZ, wl + 0*WSZ, WSZ/4);
    cvt_split<<<1024, 256>>>(Wk,  wh + 1*WSZ, wl + 1*WSZ, WSZ/4);
    cvt_split<<<1024, 256>>>(Wv,  wh + 2*WSZ, wl + 2*WSZ, WSZ/4);
    cvt_split<<<1024, 256>>>(Wve, wh + 3*WSZ, wl + 3*WSZ, WSZ/4);
    cvt_split<<<1024, 256>>>(Woe, wh + 4*WSZ, wl + 4*WSZ, WSZ/4);
    cvt_split<<<1024, 256>>>(Wo,  wh + 5*WSZ, wl + 5*WSZ, WSZ/4);

    // 2) projections -> bf16 hi/lo directly (mode 1)
    gemm_mma<<<dim3(8, 16, 4), 256, GSMEM_BYTES>>>(ah, al, wh, wl,
                                                   nullptr, ph, pl, SCALING_F, 1);

    // 3) fused QK + softmax (probs -> g_attn)
    qk_softmax<<<dim3(4, 256), 256, QK_SMEM>>>(bias, oidx, pmask, emask,
                                               ph, pl, ph + PSZ, pl + PSZ);

    // 4) fused PV + vec (tensor cores)
    pv_mma<<<dim3(4, 32, 8), 256, PV_SMEM>>>(pos, epos, oidx, pmask, emask,
                                             ph + 2*PSZ, pl + 2*PSZ,
                                             ph + 3*PSZ, pl + 3*PSZ);

    // 5) output GEMMs (mode 0)
    cvt_split<<<2048, 256>>>(xo, ah, al, (NB*NN*NE)/4);
    gemm_mma<<<dim3(8, 16, 1), 256, GSMEM_BYTES>>>(ah, al, wh + 4*WSZ, wl + 4*WSZ,
                                                   out, nullptr, nullptr, 1.0f, 0);

    cvt_split<<<6144, 256>>>(vec, ah, al, (NB*NN*3*NE)/4);
    gemm_mma<<<dim3(8, 48, 1), 256, GSMEM_BYTES>>>(ah, al, wh + 5*WSZ, wl + 5*WSZ,
                                                   out + NB*NN*NE, nullptr, nullptr, 1.0f, 0);
}

// round 5
// speedup vs baseline: 2.5446x; 1.0422x over previous
#include <cuda_runtime.h>
#include <cuda_bf16.h>
#include <float.h>
#include <math.h>
#include <stdint.h>

// Problem constants
#define NB 8
#define NN 256
#define NM 512
#define NE 1024
#define NH 32
#define ND 32
#define NEXT 768   // N + M

#define SCALING_F 0.17677669529663687f  // 32^-0.5

// ---------------- device scratch ----------------
static __device__ float g_attn[(long long)NB*NH*NN*NEXT];   // probs (fp32)
// bf16 split staging: activations for GEMM A operands.
//   [0 .. 2M)  : x rows / xo rows
//   [2M .. 8M) : vec rows
static __device__ __nv_bfloat16 g_ah[8192LL*1024];
static __device__ __nv_bfloat16 g_al[8192LL*1024];
static __device__ __nv_bfloat16 g_wh[6LL*1024*1024]; // weights hi (Wq,Wk,Wv,Wve,Woe,Wo)
static __device__ __nv_bfloat16 g_wl[6LL*1024*1024];
// projections q,k,v,ve in bf16 hi/lo ([b*n, e] row-major)
static __device__ __nv_bfloat16 g_projh[4LL*2048*1024];
static __device__ __nv_bfloat16 g_projl[4LL*2048*1024];
#define PSZ 2097152
#define VOFF 2097152   // vec region offset in g_ah/g_al

// ============================================================================
// helpers
// ============================================================================
__device__ __forceinline__ uint32_t smem_u32(const void* p) {
    uint32_t a;
    asm("{ .reg .u64 t; cvta.to.shared.u64 t, %1; cvt.u32.u64 %0, t; }"
        : "=r"(a) : "l"(p));
    return a;
}
#define CP_ASYNC16(sa, ga) \
    asm volatile("cp.async.cg.shared.global [%0], [%1], 16;\n" :: "r"(sa), "l"(ga))
#define CP_COMMIT() asm volatile("cp.async.commit_group;\n" ::: "memory")
#define CP_WAIT(n)  asm volatile("cp.async.wait_group %0;\n" :: "n"(n) : "memory")

__device__ __forceinline__ void mma16816(float* c, const uint32_t* a, const uint32_t* b) {
    asm volatile(
        "mma.sync.aligned.m16n8k16.row.col.f32.bf16.bf16.f32 "
        "{%0,%1,%2,%3}, {%4,%5,%6,%7}, {%8,%9}, {%0,%1,%2,%3};\n"
        : "+f"(c[0]), "+f"(c[1]), "+f"(c[2]), "+f"(c[3])
        : "r"(a[0]), "r"(a[1]), "r"(a[2]), "r"(a[3]), "r"(b[0]), "r"(b[1]));
}
__device__ __forceinline__ void ldsm4(uint32_t& r0, uint32_t& r1, uint32_t& r2,
                                      uint32_t& r3, uint32_t a) {
    asm volatile("ldmatrix.sync.aligned.m8n8.x4.shared.b16 {%0,%1,%2,%3}, [%4];"
                 : "=r"(r0), "=r"(r1), "=r"(r2), "=r"(r3) : "r"(a));
}

// split two floats into packed bf16 hi/lo words
__device__ __forceinline__ void split2(float a, float b, uint32_t& hi, uint32_t& lo) {
    __nv_bfloat16 h0 = __float2bfloat16(a);
    __nv_bfloat16 h1 = __float2bfloat16(b);
    __nv_bfloat16 l0 = __float2bfloat16(a - __bfloat162float(h0));
    __nv_bfloat16 l1 = __float2bfloat16(b - __bfloat162float(h1));
    __nv_bfloat162 H; H.x = h0; H.y = h1;
    __nv_bfloat162 L; L.x = l0; L.y = l1;
    hi = *(uint32_t*)&H;
    lo = *(uint32_t*)&L;
}

// ============================================================================
// converters
// ============================================================================
// x is [N, B, E]; emit row-major [B*N, E] hi/lo
__global__ __launch_bounds__(256) void cvt_split_x(const float* __restrict__ src,
                                                   __nv_bfloat16* __restrict__ hi,
                                                   __nv_bfloat16* __restrict__ lo)
{
    int i = blockIdx.x * 256 + threadIdx.x;
    int r  = i >> 8;
    int e4 = (i & 255) << 2;
    int b = r >> 8, n = r & 255;
    float4 v = *(const float4*)(src + ((long long)n * NB + b) * NE + e4);
    uint32_t h0, l0, h1, l1;
    split2(v.x, v.y, h0, l0);
    split2(v.z, v.w, h1, l1);
    ((uint2*)hi)[i] = make_uint2(h0, h1);
    ((uint2*)lo)[i] = make_uint2(l0, l1);
}

// all six weights in one launch: grid (1024, 6)
__global__ __launch_bounds__(256) void cvt_split_w(const float* __restrict__ W0,
                                                   const float* __restrict__ W1,
                                                   const float* __restrict__ W2,
                                                   const float* __restrict__ W3,
                                                   const float* __restrict__ W4,
                                                   const float* __restrict__ W5,
                                                   __nv_bfloat16* __restrict__ hi,
                                                   __nv_bfloat16* __restrict__ lo)
{
    int w = blockIdx.y;
    const float* src = (w == 0) ? W0 : (w == 1) ? W1 : (w == 2) ? W2
                     : (w == 3) ? W3 : (w == 4) ? W4 : W5;
    int i = blockIdx.x * 256 + threadIdx.x;   // 262144 quads per weight
    float4 v = ((const float4*)src)[i];
    uint32_t h0, l0, h1, l1;
    split2(v.x, v.y, h0, l0);
    split2(v.z, v.w, h1, l1);
    size_t o = ((size_t)w << 18) + i;
    ((uint2*)hi)[o] = make_uint2(h0, h1);
    ((uint2*)lo)[o] = make_uint2(l0, l1);
}

// ============================================================================
// Tensor-core split-precision GEMM: C = alpha * A @ W^T
//   mode 0: write fp32 to C.  mode 1: write bf16 hi/lo to Ch/Cl.
// ============================================================================
#define TILE_ELE 5120
#define STAGE_ELE 20480
#define GSMEM_BYTES 81920

__global__ __launch_bounds__(256, 2) void gemm_mma(const __nv_bfloat16* __restrict__ Ah,
                                                   const __nv_bfloat16* __restrict__ Al,
                                                   const __nv_bfloat16* __restrict__ Bh,
                                                   const __nv_bfloat16* __restrict__ Bl,
                                                   float* __restrict__ C,
                                                   __nv_bfloat16* __restrict__ Ch,
                                                   __nv_bfloat16* __restrict__ Cl,
                                                   float alpha0, int mode)
{
    extern __shared__ __nv_bfloat16 sm[];

    const int tid  = threadIdx.x;
    const int wid  = tid >> 5;
    const int lane = tid & 31;
    const int g    = lane >> 2;
    const int tig  = lane & 3;
    const int row0 = blockIdx.y << 7;
    const int col0 = blockIdx.x << 7;
    const int z    = blockIdx.z;
    Bh += (size_t)z << 20;
    Bl += (size_t)z << 20;
    if (mode == 0) C += (size_t)z << 21;
    else { Ch += (size_t)z << 21; Cl += (size_t)z << 21; }
    const float alpha = (z == 0) ? alpha0 : 1.0f;
    const int wm = (wid & 1) << 6;
    const int wn = (wid >> 1) << 5;

    float acc[4][4][4];
    #pragma unroll
    for (int i = 0; i < 4; i++)
        #pragma unroll
        for (int j = 0; j < 4; j++)
            #pragma unroll
            for (int q = 0; q < 4; q++) acc[i][j][q] = 0.f;

    const uint32_t smbase = smem_u32(sm);
    // ldmatrix lane offsets (bytes); row stride 40 ele = 80 B
    const uint32_t a_off = ((wm + (lane & 7) + (((lane >> 3) & 1) << 3)) * 40
                            + ((lane >> 4) << 3)) * 2;
    const uint32_t b_off = ((wn + (lane & 7) + ((lane >> 4) << 3)) * 40
                            + (((lane >> 3) & 1) << 3)) * 2;

    #define LOAD_CHUNK(kc, s)                                                     \
    {                                                                             \
        _Pragma("unroll")                                                         \
        for (int t = 0; t < 8; t++) {                                             \
            int u    = tid + (t << 8);                                            \
            int tile = u >> 9;                                                    \
            int r    = (u >> 2) & 127;                                            \
            int cu   = u & 3;                                                     \
            const __nv_bfloat16* gp;                                              \
            if      (tile == 0) gp = Ah + (size_t)(row0 + r) * 1024;              \
            else if (tile == 1) gp = Al + (size_t)(row0 + r) * 1024;              \
            else if (tile == 2) gp = Bh + (size_t)(col0 + r) * 1024;              \
            else                gp = Bl + (size_t)(col0 + r) * 1024;              \
            gp += (kc) * 32 + cu * 8;                                             \
            uint32_t sa = smbase +                                                \
                (uint32_t)(((s) * STAGE_ELE + tile * TILE_ELE + r * 40 + cu * 8) * 2); \
            CP_ASYNC16(sa, gp);                                                   \
        }                                                                         \
    }

    LOAD_CHUNK(0, 0);
    CP_COMMIT();

    for (int kc = 0; kc < 32; kc++) {
        if (kc + 1 < 32) {
            LOAD_CHUNK(kc + 1, (kc + 1) & 1);
            CP_COMMIT();
            CP_WAIT(1);
        } else {
            CP_WAIT(0);
        }
        __syncthreads();

        const uint32_t so2 = (kc & 1) * (STAGE_ELE * 2);
        const uint32_t abase = smbase + so2 + a_off;
        const uint32_t bbase = smbase + so2 + 2 * TILE_ELE * 2 + b_off;

        #pragma unroll
        for (int kk = 0; kk < 2; kk++) {
            const uint32_t kwb = kk << 5;   // 16 elements = 32 bytes per k16 step
            uint32_t ah[4][4], al[4][4], bh[4][2], bl[4][2];
            #pragma unroll
            for (int i = 0; i < 4; i++) {
                ldsm4(ah[i][0], ah[i][1], ah[i][2], ah[i][3],
                      abase + i * 1280 + kwb);
                ldsm4(al[i][0], al[i][1], al[i][2], al[i][3],
                      abase + TILE_ELE * 2 + i * 1280 + kwb);
            }
            #pragma unroll
            for (int jp = 0; jp < 2; jp++) {
                ldsm4(bh[2*jp][0], bh[2*jp][1], bh[2*jp+1][0], bh[2*jp+1][1],
                      bbase + jp * 1280 + kwb);
                ldsm4(bl[2*jp][0], bl[2*jp][1], bl[2*jp+1][0], bl[2*jp+1][1],
                      bbase + TILE_ELE * 2 + jp * 1280 + kwb);
            }
            #pragma unroll
            for (int i = 0; i < 4; i++)
                #pragma unroll
                for (int j = 0; j < 4; j++) {
                    mma16816(acc[i][j], ah[i], bh[j]);
                    mma16816(acc[i][j], ah[i], bl[j]);
                    mma16816(acc[i][j], al[i], bh[j]);
                }
        }
        __syncthreads();
    }

    // epilogue
    #pragma unroll
    for (int i = 0; i < 4; i++) {
        int row = row0 + wm + (i << 4) + g;
        #pragma unroll
        for (int j = 0; j < 4; j++) {
            int col = col0 + wn + (j << 3) + (tig << 1);
            float v0 = alpha * acc[i][j][0];
            float v1 = alpha * acc[i][j][1];
            float v2 = alpha * acc[i][j][2];
            float v3 = alpha * acc[i][j][3];
            if (mode == 0) {
                *(float2*)(C + (size_t)row * 1024 + col)       = make_float2(v0, v1);
                *(float2*)(C + (size_t)(row + 8) * 1024 + col) = make_float2(v2, v3);
            } else {
                uint32_t h0, l0, h1, l1;
                split2(v0, v1, h0, l0);
                split2(v2, v3, h1, l1);
                *(uint32_t*)(Ch + (size_t)row * 1024 + col)       = h0;
                *(uint32_t*)(Cl + (size_t)row * 1024 + col)       = l0;
                *(uint32_t*)(Ch + (size_t)(row + 8) * 1024 + col) = h1;
                *(uint32_t*)(Cl + (size_t)(row + 8) * 1024 + col) = l1;
            }
        }
    }
}

// ============================================================================
// Fused QK^T (split bf16 HMMA) + bias + mask + softmax.
// ============================================================================
#define LSTRIDE 772
#define QK_SMEM 218112

__global__ __launch_bounds__(256) void qk_softmax(const float* __restrict__ bias,
                                                  const int*   __restrict__ oidx,
                                                  const unsigned char* __restrict__ pmask,
                                                  const unsigned char* __restrict__ emask,
                                                  const __nv_bfloat16* __restrict__ qh_g,
                                                  const __nv_bfloat16* __restrict__ ql_g,
                                                  const __nv_bfloat16* __restrict__ kh_g,
                                                  const __nv_bfloat16* __restrict__ kl_g)
{
    extern __shared__ char sraw[];
    float* logits = (float*)sraw;
    __nv_bfloat16* sq = (__nv_bfloat16*)(sraw + 64 * LSTRIDE * 4);
    __nv_bfloat16* sqh = sq;
    __nv_bfloat16* sql = sq + 2560;
    __nv_bfloat16* skh = sq + 5120;
    __nv_bfloat16* skl = sq + 7680;

    const int tid  = threadIdx.x;
    const int wid  = tid >> 5;
    const int lane = tid & 31;
    const int g    = lane >> 2;
    const int tig  = lane & 3;
    const int bh   = blockIdx.y;
    const int b    = bh >> 5;
    const int h    = bh & 31;
    const int n0   = blockIdx.x << 6;

    {
        int r = tid >> 2, c = (tid & 3) << 3;
        size_t off = (size_t)(b * NN + n0 + r) * NE + h * ND + c;
        *(uint4*)(sqh + r * 40 + c) = *(const uint4*)(qh_g + off);
        *(uint4*)(sql + r * 40 + c) = *(const uint4*)(ql_g + off);
    }

    const int wn = (wid & 1) << 5;
    const int wm = (wid >> 1) << 4;

    for (int m0 = 0; m0 < NEXT; m0 += 64) {
        __syncthreads();
        {
            int r = tid >> 2, c = (tid & 3) << 3;
            int m = m0 + r;
            int row = (m < NN) ? m : oidx[b * NM + m - NN];
            size_t off = (size_t)(b * NN + row) * NE + h * ND + c;
            *(uint4*)(skh + r * 40 + c) = *(const uint4*)(kh_g + off);
            *(uint4*)(skl + r * 40 + c) = *(const uint4*)(kl_g + off);
        }
        __syncthreads();

        float acc[2][2][4];
        #pragma unroll
        for (int i = 0; i < 2; i++)
            #pragma unroll
            for (int j = 0; j < 2; j++)
                #pragma unroll
                for (int q = 0; q < 4; q++) acc[i][j][q] = 0.f;

        #pragma unroll
        for (int kk = 0; kk < 2; kk++) {
            const int kw = kk << 3;
            uint32_t ah[2][4], al[2][4], bhf[2][2], blf[2][2];
            #pragma unroll
            for (int i = 0; i < 2; i++) {
                int rA = wn + (i << 4) + g;
                ah[i][0] = *(const uint32_t*)(sqh + (rA    ) * 40 + ((kw + tig    ) << 1));
                ah[i][1] = *(const uint32_t*)(sqh + (rA + 8) * 40 + ((kw + tig    ) << 1));
                ah[i][2] = *(const uint32_t*)(sqh + (rA    ) * 40 + ((kw + tig + 4) << 1));
                ah[i][3] = *(const uint32_t*)(sqh + (rA + 8) * 40 + ((kw + tig + 4) << 1));
                al[i][0] = *(const uint32_t*)(sql + (rA    ) * 40 + ((kw + tig    ) << 1));
                al[i][1] = *(const uint32_t*)(sql + (rA + 8) * 40 + ((kw + tig    ) << 1));
                al[i][2] = *(const uint32_t*)(sql + (rA    ) * 40 + ((kw + tig + 4) << 1));
                al[i][3] = *(const uint32_t*)(sql + (rA + 8) * 40 + ((kw + tig + 4) << 1));
            }
            #pragma unroll
            for (int j = 0; j < 2; j++) {
                int rB = wm + (j << 3) + g;
                bhf[j][0] = *(const uint32_t*)(skh + rB * 40 + ((kw + tig    ) << 1));
                bhf[j][1] = *(const uint32_t*)(skh + rB * 40 + ((kw + tig + 4) << 1));
                blf[j][0] = *(const uint32_t*)(skl + rB * 40 + ((kw + tig    ) << 1));
                blf[j][1] = *(const uint32_t*)(skl + rB * 40 + ((kw + tig + 4) << 1));
            }
            #pragma unroll
            for (int i = 0; i < 2; i++)
                #pragma unroll
                for (int j = 0; j < 2; j++) {
                    mma16816(acc[i][j], ah[i], bhf[j]);
                    mma16816(acc[i][j], ah[i], blf[j]);
                    mma16816(acc[i][j], al[i], bhf[j]);
                }
        }

        #pragma unroll
        for (int i = 0; i < 2; i++) {
            int row = wn + (i << 4) + g;
            #pragma unroll
            for (int j = 0; j < 2; j++) {
                int col = m0 + wm + (j << 3) + (tig << 1);
                *(float2*)&logits[row * LSTRIDE + col]       = make_float2(acc[i][j][0], acc[i][j][1]);
                *(float2*)&logits[(row + 8) * LSTRIDE + col] = make_float2(acc[i][j][2], acc[i][j][3]);
            }
        }
    }
    __syncthreads();

    for (int rr = wid; rr < 64; rr += 8) {
        int n = n0 + rr;
        bool pn = pmask[b * NN + n] != 0;
        const float* lrow = logits + rr * LSTRIDE;
        long long goff = (((long long)(b * NH + h)) * NN + n) * NEXT;

        float val[24];
        float mx = -FLT_MAX;
        #pragma unroll
        for (int t = 0; t < 24; t++) {
            int m = lane + (t << 5);
            bool fm = (m < NN) ? (pmask[b * NN + m] != 0)
                               : (emask[b * NM + m - NN] != 0);
            float v = lrow[m] + bias[goff + m];
            if (pn || fm) v = -FLT_MAX;
            val[t] = v;
            mx = fmaxf(mx, v);
        }
        #pragma unroll
        for (int o = 16; o > 0; o >>= 1)
            mx = fmaxf(mx, __shfl_xor_sync(0xffffffffu, mx, o));
        float s = 0.f;
        #pragma unroll
        for (int t = 0; t < 24; t++) {
            val[t] = expf(val[t] - mx);
            s += val[t];
        }
        #pragma unroll
        for (int o = 16; o > 0; o >>= 1)
            s += __shfl_xor_sync(0xffffffffu, s, o);
        float inv = 1.f / s;
        #pragma unroll
        for (int t = 0; t < 24; t++)
            g_attn[goff + lane + (t << 5)] = val[t] * inv;
    }
}

// ============================================================================
// Fused PV + vec with split-bf16 HMMA + ldmatrix; epilogue writes bf16 hi/lo.
// ============================================================================
#define PV_A    4608
#define PV_VB   36864
#define PV_B    2304
#define PV_SMEM 92160

__global__ __launch_bounds__(256, 2) void pv_mma(const float* __restrict__ pos,
                                                 const float* __restrict__ epos,
                                                 const int*   __restrict__ oidx,
                                                 const unsigned char* __restrict__ pmask,
                                                 const unsigned char* __restrict__ emask,
                                                 const __nv_bfloat16* __restrict__ vh_g,
                                                 const __nv_bfloat16* __restrict__ vl_g,
                                                 const __nv_bfloat16* __restrict__ veh_g,
                                                 const __nv_bfloat16* __restrict__ vel_g,
                                                 __nv_bfloat16* __restrict__ outh,
                                                 __nv_bfloat16* __restrict__ outl)
{
    extern __shared__ __nv_bfloat16 sp[];

    const int tid  = threadIdx.x;
    const int wid  = tid >> 5;
    const int lane = tid & 31;
    const int g    = lane >> 2;
    const int tig  = lane & 3;
    const int b    = blockIdx.z;
    const int h    = blockIdx.y;
    const int n0   = blockIdx.x << 6;

    const int rowblk = (wid & 3) << 4;
    const int pair   = wid >> 2;

    __nv_bfloat16* VEh = sp + PV_VB;
    __nv_bfloat16* VEl = VEh + PV_B;
    __nv_bfloat16* Vh  = VEh + 2 * PV_B;
    __nv_bfloat16* Vl  = VEh + 3 * PV_B;

    // ldmatrix lane offsets (bytes); A row stride 72 ele = 144 B
    const uint32_t spb = smem_u32(sp);
    const uint32_t a_offp = ((rowblk + (lane & 7) + (((lane >> 3) & 1) << 3)) * 72
                             + ((lane >> 4) << 3)) * 2;
    const uint32_t b_offp = (((lane & 7) + ((lane >> 4) << 3)) * 72
                             + (((lane >> 3) & 1) << 3)) * 2;
    const uint32_t A0u = spb + (((pair == 0) ? 0 : 4) * PV_A) * 2 + a_offp;
    const uint32_t A1u = spb + (((pair == 0) ? 2 : 6) * PV_A) * 2 + a_offp;
    const uint32_t Bvb = spb + PV_VB * 2;
    const uint32_t B0u = ((pair == 0) ? Bvb : Bvb + 2 * PV_B * 2) + b_offp;
    const uint32_t B1u = Bvb + 2 * PV_B * 2 + b_offp;

    float acc0[4][4], acc1[4][4];
    #pragma unroll
    for (int j = 0; j < 4; j++)
        #pragma unroll
        for (int q = 0; q < 4; q++) { acc0[j][q] = 0.f; acc1[j][q] = 0.f; }

    const int p_n  = tid >> 2;
    const int p_mb = (tid & 3) << 4;
    const float pxn = pos[(b * NN + n0 + p_n) * 3 + 0];
    const float pyn = pos[(b * NN + n0 + p_n) * 3 + 1];
    const float pzn = pos[(b * NN + n0 + p_n) * 3 + 2];
    const bool  pnn = pmask[b * NN + n0 + p_n] != 0;

    for (int m0 = 0; m0 < NEXT; m0 += 64) {
        __syncthreads();
        // ---- phase 1a: P tile + delta -> 4 scaled A mats (hi/lo) ----
        {
            const float* prow = g_attn +
                (((long long)(b * NH + h)) * NN + n0 + p_n) * NEXT + m0 + p_mb;
            float P[16];
            *(float4*)(P + 0)  = *(const float4*)(prow + 0);
            *(float4*)(P + 4)  = *(const float4*)(prow + 4);
            *(float4*)(P + 8)  = *(const float4*)(prow + 8);
            *(float4*)(P + 12) = *(const float4*)(prow + 12);

            float pdx[16], pdy[16], pdz[16];
            #pragma unroll
            for (int q = 0; q < 16; q++) {
                int m = m0 + p_mb + q;
                float ax, ay, az; bool fm;
                if (m < NN) {
                    const float* pp = pos + (b * NN + m) * 3;
                    ax = pp[0]; ay = pp[1]; az = pp[2];
                    fm = pmask[b * NN + m] != 0;
                } else {
                    const float* pp = epos + (b * NM + m - NN) * 3;
                    ax = pp[0]; ay = pp[1]; az = pp[2];
                    fm = emask[b * NM + m - NN] != 0;
                }
                float dx = pxn - ax, dy = pyn - ay, dz = pzn - az;
                float dist = sqrtf(dx * dx + dy * dy + dz * dz);
                if (pnn || fm) dist = 1e6f;
                float inv = 1.f / (dist + 1.f);
                if (pnn) inv = 0.f;
                float Pv = P[q];
                pdx[q] = Pv * dx * inv;
                pdy[q] = Pv * dy * inv;
                pdz[q] = Pv * dz * inv;
            }
            int base = p_n * 72 + p_mb;
            #pragma unroll
            for (int qp = 0; qp < 8; qp++) {
                uint32_t hi, lo;
                split2(P[2*qp], P[2*qp+1], hi, lo);
                *(uint32_t*)(sp + 0 * PV_A + base + 2*qp) = hi;
                *(uint32_t*)(sp + 1 * PV_A + base + 2*qp) = lo;
                split2(pdx[2*qp], pdx[2*qp+1], hi, lo);
                *(uint32_t*)(sp + 2 * PV_A + base + 2*qp) = hi;
                *(uint32_t*)(sp + 3 * PV_A + base + 2*qp) = lo;
                split2(pdy[2*qp], pdy[2*qp+1], hi, lo);
                *(uint32_t*)(sp + 4 * PV_A + base + 2*qp) = hi;
                *(uint32_t*)(sp + 5 * PV_A + base + 2*qp) = lo;
                split2(pdz[2*qp], pdz[2*qp+1], hi, lo);
                *(uint32_t*)(sp + 6 * PV_A + base + 2*qp) = hi;
                *(uint32_t*)(sp + 7 * PV_A + base + 2*qp) = lo;
            }
        }
        // ---- phase 1b: v / ve tiles transposed into B mats ----
        {
            int d  = tid & 31;
            int mq = tid >> 5;
            #pragma unroll
            for (int s = 0; s < 8; s++) {
                int m = (mq << 3) + s;
                int mg = m0 + m;
                int row = (mg < NN) ? mg : oidx[b * NM + mg - NN];
                size_t off = (size_t)(b * NN + row) * NE + h * ND + d;
                VEh[d * 72 + m] = veh_g[off];
                VEl[d * 72 + m] = vel_g[off];
                Vh [d * 72 + m] = vh_g [off];
                Vl [d * 72 + m] = vl_g [off];
            }
        }
        __syncthreads();

        // ---- phase 2: MMAs (ldmatrix fragments) ----
        #pragma unroll
        for (int o = 0; o < 2; o++) {
            const uint32_t Au = o ? A1u : A0u;
            const uint32_t Bu = o ? B1u : B0u;
            float (*acc)[4] = o ? acc1 : acc0;
            #pragma unroll
            for (int kk = 0; kk < 4; kk++) {
                const uint32_t kwb = kk << 5;
                uint32_t ah[4], al[4], bh[4][2], bl[4][2];
                ldsm4(ah[0], ah[1], ah[2], ah[3], Au + kwb);
                ldsm4(al[0], al[1], al[2], al[3], Au + PV_A * 2 + kwb);
                #pragma unroll
                for (int jp = 0; jp < 2; jp++) {
                    ldsm4(bh[2*jp][0], bh[2*jp][1], bh[2*jp+1][0], bh[2*jp+1][1],
                          Bu + jp * 2304 + kwb);
                    ldsm4(bl[2*jp][0], bl[2*jp][1], bl[2*jp+1][0], bl[2*jp+1][1],
                          Bu + PV_B * 2 + jp * 2304 + kwb);
                }
                #pragma unroll
                for (int j = 0; j < 4; j++) {
                    mma16816(acc[j], ah, bh[j]);
                    mma16816(acc[j], ah, bl[j]);
                    mma16816(acc[j], al, bh[j]);
                }
            }
        }
    }

    // ---- epilogue: split to bf16 hi/lo, write to out-GEMM A buffers ----
    const int r0g = n0 + rowblk + g;
    #pragma unroll
    for (int j = 0; j < 4; j++) {
        int col = h * ND + (j << 3) + (tig << 1);
        uint32_t hi, lo;
        if (pair == 0) {
            size_t ro0 = (size_t)(b * NN + r0g) * NE + col;
            size_t ro1 = (size_t)(b * NN + r0g + 8) * NE + col;
            split2(acc0[j][0], acc0[j][1], hi, lo);
            *(uint32_t*)(outh + ro0) = hi; *(uint32_t*)(outl + ro0) = lo;
            split2(acc0[j][2], acc0[j][3], hi, lo);
            *(uint32_t*)(outh + ro1) = hi; *(uint32_t*)(outl + ro1) = lo;
            size_t vo0 = VOFF + ((size_t)(b * NN + r0g) * 3 + 0) * NE + col;
            size_t vo1 = VOFF + ((size_t)(b * NN + r0g + 8) * 3 + 0) * NE + col;
            split2(acc1[j][0], acc1[j][1], hi, lo);
            *(uint32_t*)(outh + vo0) = hi; *(uint32_t*)(outl + vo0) = lo;
            split2(acc1[j][2], acc1[j][3], hi, lo);
            *(uint32_t*)(outh + vo1) = hi; *(uint32_t*)(outl + vo1) = lo;
        } else {
            size_t vo0 = VOFF + ((size_t)(b * NN + r0g) * 3 + 1) * NE + col;
            size_t vo1 = VOFF + ((size_t)(b * NN + r0g + 8) * 3 + 1) * NE + col;
            split2(acc0[j][0], acc0[j][1], hi, lo);
            *(uint32_t*)(outh + vo0) = hi; *(uint32_t*)(outl + vo0) = lo;
            split2(acc0[j][2], acc0[j][3], hi, lo);
            *(uint32_t*)(outh + vo1) = hi; *(uint32_t*)(outl + vo1) = lo;
            size_t wo0 = VOFF + ((size_t)(b * NN + r0g) * 3 + 2) * NE + col;
            size_t wo1 = VOFF + ((size_t)(b * NN + r0g + 8) * 3 + 2) * NE + col;
            split2(acc1[j][0], acc1[j][1], hi, lo);
            *(uint32_t*)(outh + wo0) = hi; *(uint32_t*)(outl + wo0) = lo;
            split2(acc1[j][2], acc1[j][3], hi, lo);
            *(uint32_t*)(outh + wo1) = hi; *(uint32_t*)(outl + wo1) = lo;
        }
    }
}

// ============================================================================
// launch
// ============================================================================
extern "C" void kernel_launch(void* const* d_in, const int* in_sizes, int n_in,
                              void* d_out, int out_size)
{
    const float* x    = (const float*)d_in[0];
    const float* pos  = (const float*)d_in[1];
    const float* epos = (const float*)d_in[2];
    const float* bias = (const float*)d_in[3];
    const unsigned char* pmask = (const unsigned char*)d_in[4];
    const unsigned char* emask = (const unsigned char*)d_in[5];
    const int*   oidx = (const int*)d_in[6];
    const float* Wq   = (const float*)d_in[7];
    const float* Wk   = (const float*)d_in[8];
    const float* Wv   = (const float*)d_in[9];
    const float* Wve  = (const float*)d_in[10];
    const float* Wo   = (const float*)d_in[11];
    const float* Woe  = (const float*)d_in[12];
    float* out = (float*)d_out;

    __nv_bfloat16 *ah, *al, *wh, *wl, *ph, *pl;
    cudaGetSymbolAddress((void**)&ah,  g_ah);
    cudaGetSymbolAddress((void**)&al,  g_al);
    cudaGetSymbolAddress((void**)&wh,  g_wh);
    cudaGetSymbolAddress((void**)&wl,  g_wl);
    cudaGetSymbolAddress((void**)&ph,  g_projh);
    cudaGetSymbolAddress((void**)&pl,  g_projl);

    cudaFuncSetAttribute(gemm_mma,   cudaFuncAttributeMaxDynamicSharedMemorySize, GSMEM_BYTES);
    cudaFuncSetAttribute(qk_softmax, cudaFuncAttributeMaxDynamicSharedMemorySize, QK_SMEM);
    cudaFuncSetAttribute(pv_mma,     cudaFuncAttributeMaxDynamicSharedMemorySize, PV_SMEM);

    const int WSZ = 1024 * 1024;

    // 1) converters (x permuted; all 6 weights in one launch)
    cvt_split_x<<<2048, 256>>>(x, ah, al);
    cvt_split_w<<<dim3(1024, 6), 256>>>(Wq, Wk, Wv, Wve, Woe, Wo, wh, wl);

    // 2) projections -> bf16 hi/lo directly (mode 1)
    gemm_mma<<<dim3(8, 16, 4), 256, GSMEM_BYTES>>>(ah, al, wh, wl,
                                                   nullptr, ph, pl, SCALING_F, 1);

    // 3) fused QK + softmax
    qk_softmax<<<dim3(4, 256), 256, QK_SMEM>>>(bias, oidx, pmask, emask,
                                               ph, pl, ph + PSZ, pl + PSZ);

    // 4) fused PV + vec -> bf16 hi/lo A-buffers for out GEMMs
    pv_mma<<<dim3(4, 32, 8), 256, PV_SMEM>>>(pos, epos, oidx, pmask, emask,
                                             ph + 2*PSZ, pl + 2*PSZ,
                                             ph + 3*PSZ, pl + 3*PSZ,
                                             ah, al);

    // 5) output GEMMs (mode 0): xo @ Woe^T, vec @ Wo^T
    gemm_mma<<<dim3(8, 16, 1), 256, GSMEM_BYTES>>>(ah, al, wh + 4*WSZ, wl + 4*WSZ,
                                                   out, nullptr, nullptr, 1.0f, 0);
    gemm_mma<<<dim3(8, 48, 1), 256, GSMEM_BYTES>>>(ah + VOFF, al + VOFF,
                                                   wh + 5*WSZ, wl + 5*WSZ,
                                                   out + NB*NN*NE, nullptr, nullptr, 1.0f, 0);
}